// round 3
// baseline (speedup 1.0000x reference)
#include <cuda_runtime.h>
#include <math.h>

#define NN 50000
#define EE 800000
#define FF 256
#define NF (NN*FF)            // 12,800,000
#define EF (EE*FF)            // 204,800,000
#define LL 4

// ------------------------- scratch (device globals, no allocs) -------------
__device__ float g_eA[EF];
__device__ float g_eB[EF];
__device__ float g_etmp[EF];
__device__ float g_hA[NF];
__device__ float g_hB[NF];
__device__ float g_hW[5*NF];     // hWs | hWd | hself | hWf | hWb
__device__ float g_agg[2*NF];    // agg_f | agg_b
__device__ float g_htmp[NF];
__device__ float g_logf[EE];
__device__ float g_logb[EE];
__device__ float g_exf[EE];
__device__ float g_exb[EE];
__device__ float g_mf[NN];
__device__ float g_mb[NN];
__device__ float g_denf[NN];
__device__ float g_denb[NN];
__device__ float g_cols[8*FF];   // sum_e|sumsq_e|scale_e|shift_e|sum_h|sumsq_h|scale_h|shift_h

// ------------------------- helpers ----------------------------------------
__device__ __forceinline__ void atomicMaxF(float* a, float v) {
    int* ai = (int*)a;
    int old = __float_as_int(*a);
    while (__int_as_float(old) < v) {
        int prev = atomicCAS(ai, old, __float_as_int(v));
        if (prev == old) break;
        old = prev;
    }
}

// ------------------------- GEMM: C[M,256] = A[M,256] @ W[256,256] ----------
// BM=BN=64, BK=16, 256 threads, 4x4 microtile per thread.
// EDGE: C += hWs[src[row]] + hWd[dst[row]]  (gather epilogue)
template<bool EDGE>
__device__ __forceinline__ void gemm_body(
    const float* __restrict__ A, const float* __restrict__ W, float* __restrict__ C,
    int M, const int* __restrict__ src, const int* __restrict__ dst,
    const float4* __restrict__ gs, const float4* __restrict__ gd)
{
    __shared__ float As[16][68];   // padded: stride 68 floats (16B-aligned rows)
    __shared__ float Bs[16][64];
    const int tid  = threadIdx.x;
    const int tx   = tid & 15, ty = tid >> 4;
    const int bm   = blockIdx.y, bn = blockIdx.x;
    const int rowA = tid >> 2;
    const int kA   = (tid & 3) << 2;
    const int kB   = tid >> 4;
    const int nB   = (tid & 15) << 2;
    const int arow = bm*64 + rowA;
    const float4* A4 = (const float4*)A;
    const float4* W4 = (const float4*)W;
    float acc[4][4] = {};

    for (int kt = 0; kt < FF; kt += 16) {
        float4 a = make_float4(0.f,0.f,0.f,0.f);
        if (arow < M) a = A4[arow*64 + ((kt + kA) >> 2)];
        float4 b = W4[(kt + kB)*64 + bn*16 + (nB >> 2)];
        __syncthreads();
        As[kA+0][rowA] = a.x; As[kA+1][rowA] = a.y;
        As[kA+2][rowA] = a.z; As[kA+3][rowA] = a.w;
        *(float4*)&Bs[kB][nB] = b;
        __syncthreads();
        #pragma unroll
        for (int k = 0; k < 16; k++) {
            float4 av = *(const float4*)&As[k][ty << 2];
            float4 bv = *(const float4*)&Bs[k][tx << 2];
            float ar[4] = {av.x, av.y, av.z, av.w};
            float br[4] = {bv.x, bv.y, bv.z, bv.w};
            #pragma unroll
            for (int i = 0; i < 4; i++)
                #pragma unroll
                for (int j = 0; j < 4; j++)
                    acc[i][j] += ar[i] * br[j];
        }
    }

    #pragma unroll
    for (int i = 0; i < 4; i++) {
        int gm = bm*64 + (ty << 2) + i;
        if (gm < M) {
            float4 r = make_float4(acc[i][0], acc[i][1], acc[i][2], acc[i][3]);
            int cidx = gm*64 + bn*16 + tx;
            if (EDGE) {
                int s = src[gm], d = dst[gm];
                float4 x = gs[s*64 + bn*16 + tx];
                float4 y = gd[d*64 + bn*16 + tx];
                r.x += x.x + y.x; r.y += x.y + y.y;
                r.z += x.z + y.z; r.w += x.w + y.w;
            }
            ((float4*)C)[cidx] = r;
        }
    }
}

struct G5 { const float* W[5]; float* O[5]; };

__global__ __launch_bounds__(256) void gemm5_k(const float* __restrict__ A, G5 p, int M) {
    gemm_body<false>(A, p.W[blockIdx.z], p.O[blockIdx.z], M, nullptr, nullptr, nullptr, nullptr);
}

__global__ __launch_bounds__(256) void gemm_edge_k(
    const float* __restrict__ A, const float* __restrict__ W, float* __restrict__ C, int M,
    const int* __restrict__ src, const int* __restrict__ dst,
    const float4* __restrict__ gs, const float4* __restrict__ gd) {
    gemm_body<true>(A, W, C, M, src, dst, gs, gd);
}

// ------------------------- init kernels ------------------------------------
__global__ void init_k(float* mf, float* mb, float* denf, float* denb, float* cols) {
    int i = blockIdx.x*blockDim.x + threadIdx.x;
    if (i < NN) { mf[i] = -INFINITY; mb[i] = -INFINITY; denf[i] = 0.f; denb[i] = 0.f; }
    if (i < 8*FF) cols[i] = 0.f;
}

__global__ void zero4_k(float4* p, int n4) {
    int i = blockIdx.x*blockDim.x + threadIdx.x;
    if (i < n4) p[i] = make_float4(0.f,0.f,0.f,0.f);
}

// ------- pass over e_tmp: attention logits + segment max + BN col stats ----
__global__ void logits_stats_k(
    const float* __restrict__ etmp, const float* __restrict__ af, const float* __restrict__ ab,
    const int* __restrict__ src, const int* __restrict__ dst,
    float* __restrict__ logf, float* __restrict__ logb,
    float* __restrict__ mf, float* __restrict__ mb,
    float* __restrict__ colsum, float* __restrict__ colsumsq)
{
    const int lane = threadIdx.x & 31;
    const int warp = (blockIdx.x*blockDim.x + threadIdx.x) >> 5;
    const int nwarps = (gridDim.x*blockDim.x) >> 5;
    const float4* et4 = (const float4*)etmp;
    const float4 af0 = ((const float4*)af)[lane], af1 = ((const float4*)af)[lane+32];
    const float4 ab0 = ((const float4*)ab)[lane], ab1 = ((const float4*)ab)[lane+32];
    float4 cs0 = make_float4(0,0,0,0), cs1 = cs0, cq0 = cs0, cq1 = cs0;

    for (int r = warp; r < EE; r += nwarps) {
        float4 v0 = et4[r*64 + lane];
        float4 v1 = et4[r*64 + 32 + lane];
        float df = v0.x*af0.x + v0.y*af0.y + v0.z*af0.z + v0.w*af0.w
                 + v1.x*af1.x + v1.y*af1.y + v1.z*af1.z + v1.w*af1.w;
        float db = v0.x*ab0.x + v0.y*ab0.y + v0.z*ab0.z + v0.w*ab0.w
                 + v1.x*ab1.x + v1.y*ab1.y + v1.z*ab1.z + v1.w*ab1.w;
        cs0.x += v0.x; cs0.y += v0.y; cs0.z += v0.z; cs0.w += v0.w;
        cs1.x += v1.x; cs1.y += v1.y; cs1.z += v1.z; cs1.w += v1.w;
        cq0.x += v0.x*v0.x; cq0.y += v0.y*v0.y; cq0.z += v0.z*v0.z; cq0.w += v0.w*v0.w;
        cq1.x += v1.x*v1.x; cq1.y += v1.y*v1.y; cq1.z += v1.z*v1.z; cq1.w += v1.w*v1.w;
        #pragma unroll
        for (int off = 16; off > 0; off >>= 1) {
            df += __shfl_xor_sync(0xFFFFFFFFu, df, off);
            db += __shfl_xor_sync(0xFFFFFFFFu, db, off);
        }
        if (lane == 0) {
            float lf = df > 0.f ? df : 0.2f*df;
            float lb = db > 0.f ? db : 0.2f*db;
            logf[r] = lf; logb[r] = lb;
            atomicMaxF(&mf[dst[r]], lf);
            atomicMaxF(&mb[src[r]], lb);
        }
    }
    int c0 = lane*4, c1 = 128 + lane*4;
    atomicAdd(&colsum[c0+0], cs0.x); atomicAdd(&colsum[c0+1], cs0.y);
    atomicAdd(&colsum[c0+2], cs0.z); atomicAdd(&colsum[c0+3], cs0.w);
    atomicAdd(&colsum[c1+0], cs1.x); atomicAdd(&colsum[c1+1], cs1.y);
    atomicAdd(&colsum[c1+2], cs1.z); atomicAdd(&colsum[c1+3], cs1.w);
    atomicAdd(&colsumsq[c0+0], cq0.x); atomicAdd(&colsumsq[c0+1], cq0.y);
    atomicAdd(&colsumsq[c0+2], cq0.z); atomicAdd(&colsumsq[c0+3], cq0.w);
    atomicAdd(&colsumsq[c1+0], cq1.x); atomicAdd(&colsumsq[c1+1], cq1.y);
    atomicAdd(&colsumsq[c1+2], cq1.z); atomicAdd(&colsumsq[c1+3], cq1.w);
}

__global__ void finalize_bn_k(const float* __restrict__ colsum, const float* __restrict__ colsumsq,
                              const float* __restrict__ g, const float* __restrict__ b,
                              float invM, float* __restrict__ scale, float* __restrict__ shift) {
    int f = threadIdx.x;
    float mean = colsum[f] * invM;
    float var  = colsumsq[f] * invM - mean*mean;
    float sc   = g[f] * rsqrtf(var + 1e-5f);
    scale[f] = sc;
    shift[f] = b[f] - mean * sc;
}

__global__ void exp_k(const float* __restrict__ logf, const float* __restrict__ logb,
                      const int* __restrict__ src, const int* __restrict__ dst,
                      const float* __restrict__ mf, const float* __restrict__ mb,
                      float* __restrict__ exf, float* __restrict__ exb,
                      float* __restrict__ denf, float* __restrict__ denb) {
    int i = blockIdx.x*blockDim.x + threadIdx.x;
    if (i >= EE) return;
    int d = dst[i], s = src[i];
    float ef = expf(logf[i] - mf[d]);
    float eb = expf(logb[i] - mb[s]);
    exf[i] = ef; exb[i] = eb;
    atomicAdd(&denf[d], ef);
    atomicAdd(&denb[s], eb);
}

// out = base + relu(x*scale + shift), rows of 256 cols, vectorized float4
__global__ void residual_bn_k(const float* __restrict__ base, const float* __restrict__ x,
                              const float* __restrict__ scale, const float* __restrict__ shift,
                              float* __restrict__ out, int n4) {
    int i = blockIdx.x*blockDim.x + threadIdx.x;
    if (i >= n4) return;
    int c4 = i & 63;
    float4 v  = ((const float4*)x)[i];
    float4 bs = ((const float4*)base)[i];
    float4 sc = ((const float4*)scale)[c4];
    float4 sh = ((const float4*)shift)[c4];
    float4 r;
    r.x = bs.x + fmaxf(v.x*sc.x + sh.x, 0.f);
    r.y = bs.y + fmaxf(v.y*sc.y + sh.y, 0.f);
    r.z = bs.z + fmaxf(v.z*sc.z + sh.z, 0.f);
    r.w = bs.w + fmaxf(v.w*sc.w + sh.w, 0.f);
    ((float4*)out)[i] = r;
}

// agg_f[dst] += alpha_f * hWf[src];  agg_b[src] += alpha_b * hWb[dst]
__global__ void aggregate_k(const float* __restrict__ exf, const float* __restrict__ denf,
                            const float* __restrict__ exb, const float* __restrict__ denb,
                            const int* __restrict__ src, const int* __restrict__ dst,
                            const float4* __restrict__ hWf, const float4* __restrict__ hWb,
                            float* __restrict__ aggf, float* __restrict__ aggb) {
    int idx = blockIdx.x*blockDim.x + threadIdx.x;   // exactly E*64 threads
    int e = idx >> 6, c = idx & 63;
    int s = src[e], d = dst[e];
    float af = exf[e] / (denf[d] + 1e-9f);
    float ab = exb[e] / (denb[s] + 1e-9f);
    float4 vf = hWf[s*64 + c];
    float4 vb = hWb[d*64 + c];
    float* pf = aggf + (d*64 + c)*4;
    float* pb = aggb + (s*64 + c)*4;
    atomicAdd(pf+0, vf.x*af); atomicAdd(pf+1, vf.y*af);
    atomicAdd(pf+2, vf.z*af); atomicAdd(pf+3, vf.w*af);
    atomicAdd(pb+0, vb.x*ab); atomicAdd(pb+1, vb.y*ab);
    atomicAdd(pb+2, vb.z*ab); atomicAdd(pb+3, vb.w*ab);
}

// h_tmp = hself + agg_f + agg_b, plus BN column stats
__global__ void node_stats_k(const float* __restrict__ hself, const float* __restrict__ aggf,
                             const float* __restrict__ aggb, float* __restrict__ htmp,
                             float* __restrict__ colsum, float* __restrict__ colsumsq) {
    int c = threadIdx.x;
    int r0 = blockIdx.x * 256;
    int r1 = min(r0 + 256, NN);
    float s = 0.f, q = 0.f;
    for (int r = r0; r < r1; r++) {
        int idx = r*256 + c;
        float v = hself[idx] + aggf[idx] + aggb[idx];
        htmp[idx] = v;
        s += v; q += v*v;
    }
    atomicAdd(&colsum[c], s);
    atomicAdd(&colsumsq[c], q);
}

// ------------------------- host orchestration ------------------------------
static float* symAddr(const void* sym) {
    void* p = nullptr;
    cudaGetSymbolAddress(&p, sym);
    return (float*)p;
}

extern "C" void kernel_launch(void* const* d_in, const int* in_sizes, int n_in,
                              void* d_out, int out_size) {
    const float* h0   = (const float*)d_in[0];
    const float* e0   = (const float*)d_in[1];
    const int*   src  = (const int*)d_in[2];
    const int*   dst  = (const int*)d_in[3];
    const float* We   = (const float*)d_in[4];
    const float* Ws   = (const float*)d_in[5];
    const float* Wd   = (const float*)d_in[6];
    const float* Wse  = (const float*)d_in[7];
    const float* Wf   = (const float*)d_in[8];
    const float* Wb   = (const float*)d_in[9];
    const float* attf = (const float*)d_in[10];
    const float* attb = (const float*)d_in[11];
    const float* ge   = (const float*)d_in[12];
    const float* be   = (const float*)d_in[13];
    const float* gh   = (const float*)d_in[14];
    const float* bh   = (const float*)d_in[15];

    float* eA   = symAddr(g_eA);
    float* eB   = symAddr(g_eB);
    float* etmp = symAddr(g_etmp);
    float* hA   = symAddr(g_hA);
    float* hB   = symAddr(g_hB);
    float* hW   = symAddr(g_hW);
    float* agg  = symAddr(g_agg);
    float* htmp = symAddr(g_htmp);
    float* logf = symAddr(g_logf);
    float* logb = symAddr(g_logb);
    float* exf  = symAddr(g_exf);
    float* exb  = symAddr(g_exb);
    float* mf   = symAddr(g_mf);
    float* mb   = symAddr(g_mb);
    float* denf = symAddr(g_denf);
    float* denb = symAddr(g_denb);
    float* cols = symAddr(g_cols);

    float* hWs = hW;           float* hWd = hW + NF;
    float* hse = hW + 2*NF;    float* hWf_ = hW + 3*NF;
    float* hWb_ = hW + 4*NF;
    float* aggf = agg;         float* aggb = agg + NF;

    float* cse = cols;         float* cqe = cols + FF;
    float* sce = cols + 2*FF;  float* she = cols + 3*FF;
    float* csh = cols + 4*FF;  float* cqh = cols + 5*FF;
    float* sch = cols + 6*FF;  float* shh = cols + 7*FF;

    // final outputs: reference returns (h, e) -> concat h then e
    float* outH; float* outE;
    if (out_size >= NF + EF)      { outH = (float*)d_out; outE = (float*)d_out + NF; }
    else if (out_size == EF)      { outE = (float*)d_out; outH = hB; }
    else                          { outH = (float*)d_out; outE = eB; }

    const float* hin = h0;
    const float* ein = e0;

    for (int l = 0; l < LL; l++) {
        const float* We_l = We  + (size_t)l*FF*FF;
        G5 p;
        p.W[0] = Ws  + (size_t)l*FF*FF;  p.O[0] = hWs;
        p.W[1] = Wd  + (size_t)l*FF*FF;  p.O[1] = hWd;
        p.W[2] = Wse + (size_t)l*FF*FF;  p.O[2] = hse;
        p.W[3] = Wf  + (size_t)l*FF*FF;  p.O[3] = hWf_;
        p.W[4] = Wb  + (size_t)l*FF*FF;  p.O[4] = hWb_;
        const float* af_l = attf + l*FF;
        const float* ab_l = attb + l*FF;

        float* hout; float* eout;
        if (l == LL-1)      { hout = outH; eout = outE; }
        else if (l & 1)     { hout = hB;   eout = eB;   }
        else                { hout = hA;   eout = eA;   }

        // --- init per-layer scratch ---
        init_k<<<(NN + 255)/256, 256>>>(mf, mb, denf, denb, cols);
        zero4_k<<<(2*NF/4 + 255)/256, 256>>>((float4*)agg, 2*NF/4);

        // --- node GEMMs: h @ {Ws, Wd, Wself, Wf, Wb} ---
        gemm5_k<<<dim3(4, (NN + 63)/64, 5), 256>>>(hin, p, NN);

        // --- edge GEMM: e_tmp = e @ We + hWs[src] + hWd[dst] ---
        gemm_edge_k<<<dim3(4, EE/64), 256>>>(ein, We_l, etmp, EE, src, dst,
                                             (const float4*)hWs, (const float4*)hWd);

        // --- logits + segment max + BN stats (one pass over e_tmp) ---
        logits_stats_k<<<296, 256>>>(etmp, af_l, ab_l, src, dst,
                                     logf, logb, mf, mb, cse, cqe);

        // --- finalize e-BN, exp + denominators ---
        finalize_bn_k<<<1, 256>>>(cse, cqe, ge + l*FF, be + l*FF, 1.0f/EE, sce, she);
        exp_k<<<(EE + 255)/256, 256>>>(logf, logb, src, dst, mf, mb, exf, exb, denf, denb);

        // --- e_new = e + relu(bn(e_tmp)) ---
        residual_bn_k<<<(EE*64 + 255)/256, 256>>>(ein, etmp, sce, she, eout, EE*64);

        // --- attention aggregation (scatter-add) ---
        aggregate_k<<<EE*64/256, 256>>>(exf, denf, exb, denb, src, dst,
                                        (const float4*)hWf_, (const float4*)hWb_, aggf, aggb);

        // --- node update: h_tmp = hself + agg_f + agg_b, BN stats ---
        node_stats_k<<<(NN + 255)/256, 256>>>(hse, aggf, aggb, htmp, csh, cqh);
        finalize_bn_k<<<1, 256>>>(csh, cqh, gh + l*FF, bh + l*FF, 1.0f/NN, sch, shh);

        // --- h_new = h + relu(bn(h_tmp)) ---
        residual_bn_k<<<(NN*64 + 255)/256, 256>>>(hin, htmp, sch, shh, hout, NN*64);

        hin = hout;
        ein = eout;
    }
}

// round 5
// speedup vs baseline: 1.4759x; 1.4759x over previous
#include <cuda_runtime.h>
#include <cuda_bf16.h>
#include <math.h>
#include <stdint.h>

#define NN 50000
#define EE 800000
#define FF 256
#define NF (NN*FF)            // 12,800,000
#define EF (EE*FF)            // 204,800,000
#define LL 4
#define WSZ (256*768)

// GEMM tiling
#define BM 64
#define BN 256
#define BK 64
#define AST 72                 // A smem stride in halves (64 + 8 pad)
#define BST 72                 // B smem stride in halves
#define ABYTES (BM*AST*2)      // 9216
#define BBYTES (BN*BST*2)      // 36864
#define BUFB (ABYTES + BBYTES) // 46080
#define SMEMB (2*BUFB)         // 92160

// ------------------------- scratch (device globals, no allocs) -------------
__device__ float g_eA[EF];
__device__ float g_eB[EF];
__device__ float g_etmp[EF];
__device__ float g_hA[NF];
__device__ float g_hB[NF];
__device__ float g_hW[5*NF];     // hWs | hWd | hself | hWf | hWb
__device__ float g_agg[2*NF];    // agg_f | agg_b
__device__ float g_htmp[NF];
__device__ float g_logf[EE];
__device__ float g_logb[EE];
__device__ float g_exf[EE];
__device__ float g_exb[EE];
__device__ float g_mf[NN];
__device__ float g_mb[NN];
__device__ float g_denf[NN];
__device__ float g_denb[NN];
__device__ float g_cols[8*FF];
__device__ __nv_bfloat16 g_hhi[NF];
__device__ __nv_bfloat16 g_hlo[NF];
__device__ __nv_bfloat16 g_ehi[EF];
__device__ __nv_bfloat16 g_elo[EF];
__device__ __nv_bfloat16 g_Wt[LL*6*WSZ];   // [l][w][n=256][k=768] K-major: [Whi;Whi;Wlo]

// ------------------------- helpers -----------------------------------------
__device__ __forceinline__ uint32_t s2u(const void* p) {
    uint32_t a;
    asm("{ .reg .u64 t; cvta.to.shared.u64 t, %1; cvt.u32.u64 %0, t; }" : "=r"(a) : "l"(p));
    return a;
}

__device__ __forceinline__ void cp_async16(uint32_t saddr, const void* g) {
    asm volatile("cp.async.cg.shared.global [%0], [%1], 16;" :: "r"(saddr), "l"(g));
}

__device__ __forceinline__ void ldsm4(uint32_t addr, uint32_t& r0, uint32_t& r1,
                                      uint32_t& r2, uint32_t& r3) {
    asm volatile("ldmatrix.sync.aligned.m8n8.x4.shared.b16 {%0,%1,%2,%3}, [%4];"
                 : "=r"(r0), "=r"(r1), "=r"(r2), "=r"(r3) : "r"(addr));
}

__device__ __forceinline__ void mma16816(float* d, const uint32_t* a, const uint32_t* b) {
    asm volatile(
        "mma.sync.aligned.m16n8k16.row.col.f32.bf16.bf16.f32 "
        "{%0,%1,%2,%3}, {%4,%5,%6,%7}, {%8,%9}, {%0,%1,%2,%3};"
        : "+f"(d[0]), "+f"(d[1]), "+f"(d[2]), "+f"(d[3])
        : "r"(a[0]), "r"(a[1]), "r"(a[2]), "r"(a[3]), "r"(b[0]), "r"(b[1]));
}

__device__ __forceinline__ void atomicMaxF(float* a, float v) {
    int* ai = (int*)a;
    int old = __float_as_int(*a);
    while (__int_as_float(old) < v) {
        int prev = atomicCAS(ai, old, __float_as_int(v));
        if (prev == old) break;
        old = prev;
    }
}

// ------------------------- bf16 mma.sync GEMM -------------------------------
// C[tile*64 .. +64, 0..256) = A'[.,768] @ B'[768,256], 3-term bf16 hi/lo split.
// Chunk c (0..11): A cols (c%4)*64 from (4<=c<8 ? Alo : Ahi); B rows k = c*64.
// EDGE: epilogue adds gs[src[row]] + gd[dst[row]].
template<bool EDGE>
__device__ __forceinline__ void mma_gemm(
    const __nv_bfloat16* __restrict__ Ahi, const __nv_bfloat16* __restrict__ Alo,
    const __nv_bfloat16* __restrict__ Bt, float* __restrict__ C, int M, int tile,
    const int* __restrict__ src, const int* __restrict__ dst,
    const float* __restrict__ gs, const float* __restrict__ gd)
{
    extern __shared__ __align__(16) char smem[];
    const uint32_t sb = s2u(smem);
    const int tid = threadIdx.x, wid = tid >> 5, lane = tid & 31;
    const int m0 = tile * BM;

    // --- async loader ---
    auto load_chunk = [&](int c, int buf) {
        const __nv_bfloat16* As = (c >= 4 && c < 8) ? Alo : Ahi;
        const int acol = (c & 3) << 6;
        const int kb = c << 6;
        const uint32_t ab = sb + buf*BUFB;
        const uint32_t bb = ab + ABYTES;
        #pragma unroll
        for (int i = 0; i < 2; i++) {            // A: 64x64 halves = 512 uint4
            int v = tid + (i << 8); int r = v >> 3, c16 = v & 7;
            uint32_t sa = ab + (r*AST + (c16 << 3))*2;
            int gr = m0 + r;
            if (gr < M) cp_async16(sa, As + (size_t)gr*256 + acol + (c16 << 3));
            else asm volatile("st.shared.v4.b32 [%0], {%1,%1,%1,%1};" :: "r"(sa), "r"(0));
        }
        #pragma unroll
        for (int i = 0; i < 8; i++) {            // B: 256x64 halves = 2048 uint4
            int v = tid + (i << 8); int r = v >> 3, c16 = v & 7;
            cp_async16(bb + (r*BST + (c16 << 3))*2, Bt + r*768 + kb + (c16 << 3));
        }
        asm volatile("cp.async.commit_group;");
    };

    // --- per-warp fragment base offsets ---
    const int wm = (wid & 1) << 5;               // 0 or 32 (warp M rows)
    const int wn = (wid >> 1) << 6;              // 0,64,128,192 (warp N cols)
    uint32_t a_off[2];
    #pragma unroll
    for (int im = 0; im < 2; im++)
        a_off[im] = ((wm + im*16 + (lane & 15))*AST + ((lane >> 4) << 3))*2;
    const uint32_t b_off = ((wn + ((lane >> 4) << 3) + (lane & 7))*BST
                           + (((lane >> 3) & 1) << 3))*2;

    float acc[2][8][4];
    #pragma unroll
    for (int im = 0; im < 2; im++)
        #pragma unroll
        for (int j = 0; j < 8; j++)
            #pragma unroll
            for (int q = 0; q < 4; q++) acc[im][j][q] = 0.f;

    load_chunk(0, 0);
    int buf = 0;
    for (int c = 0; c < 12; c++) {
        if (c < 11) {
            load_chunk(c + 1, buf ^ 1);
            asm volatile("cp.async.wait_group 1;");
        } else {
            asm volatile("cp.async.wait_group 0;");
        }
        __syncthreads();
        const uint32_t ab = sb + buf*BUFB;
        const uint32_t bb = ab + ABYTES;
        #pragma unroll
        for (int ks = 0; ks < 4; ks++) {
            const uint32_t kh2 = (ks << 4)*2;    // 16 halves = 32 bytes
            uint32_t a[2][4], b[8][2];
            ldsm4(ab + a_off[0] + kh2, a[0][0], a[0][1], a[0][2], a[0][3]);
            ldsm4(ab + a_off[1] + kh2, a[1][0], a[1][1], a[1][2], a[1][3]);
            #pragma unroll
            for (int jp = 0; jp < 4; jp++)
                ldsm4(bb + b_off + jp*(16*BST*2) + kh2,
                      b[2*jp][0], b[2*jp][1], b[2*jp+1][0], b[2*jp+1][1]);
            #pragma unroll
            for (int im = 0; im < 2; im++)
                #pragma unroll
                for (int j = 0; j < 8; j++)
                    mma16816(acc[im][j], a[im], b[j]);
        }
        __syncthreads();
        buf ^= 1;
    }

    // --- epilogue ---
    const int gr0 = lane >> 2;
    const int cl0 = (lane & 3) << 1;
    #pragma unroll
    for (int im = 0; im < 2; im++) {
        #pragma unroll
        for (int half = 0; half < 2; half++) {
            int gm = m0 + wm + im*16 + gr0 + half*8;
            if (gm >= M) continue;
            int s = 0, d = 0;
            if (EDGE) { s = src[gm]; d = dst[gm]; }
            #pragma unroll
            for (int j = 0; j < 8; j++) {
                int col = wn + (j << 3) + cl0;
                float2 o = make_float2(acc[im][j][half*2], acc[im][j][half*2 + 1]);
                if (EDGE) {
                    float2 x = *(const float2*)(gs + (size_t)s*256 + col);
                    float2 y = *(const float2*)(gd + (size_t)d*256 + col);
                    o.x += x.x + y.x; o.y += x.y + y.y;
                }
                *(float2*)(C + (size_t)gm*256 + col) = o;
            }
        }
    }
}

struct O5 { float* O[5]; };

__global__ __launch_bounds__(256)
void node_mma_k(const __nv_bfloat16* __restrict__ Ahi, const __nv_bfloat16* __restrict__ Alo,
                const __nv_bfloat16* __restrict__ WtL, O5 p, int M) {
    mma_gemm<false>(Ahi, Alo, WtL + (size_t)(blockIdx.z + 1)*WSZ, p.O[blockIdx.z],
                    M, blockIdx.x, nullptr, nullptr, nullptr, nullptr);
}

__global__ __launch_bounds__(256)
void edge_mma_k(const __nv_bfloat16* __restrict__ Ahi, const __nv_bfloat16* __restrict__ Alo,
                const __nv_bfloat16* __restrict__ WtL, float* __restrict__ C,
                const int* __restrict__ src, const int* __restrict__ dst,
                const float* __restrict__ gs, const float* __restrict__ gd) {
    mma_gemm<true>(Ahi, Alo, WtL, C, EE, blockIdx.x, src, dst, gs, gd);
}

// ------------------------- prep kernels ------------------------------------
struct W6 { const float* p[6]; };

// Wt[l][w][n][k]: k<512 -> bf16_hi(W[k%256][n]); k>=512 -> bf16_lo
__global__ void prep_w_k(W6 w, __nv_bfloat16* __restrict__ out) {
    long idx = (long)blockIdx.x * 256 + threadIdx.x;
    int k = (int)(idx % 768); long t = idx / 768;
    int n = (int)(t % 256);   t /= 256;
    int wi = (int)(t % 6);    int l = (int)(t / 6);
    int k2 = k & 255;
    float v = w.p[wi][((size_t)l * 256 + k2) * 256 + n];
    __nv_bfloat16 h = __float2bfloat16(v);
    out[idx] = (k < 512) ? h : __float2bfloat16(v - __bfloat162float(h));
}

__global__ void cvt_k(const float4* __restrict__ x, __nv_bfloat162* __restrict__ hi,
                      __nv_bfloat162* __restrict__ lo, int n4) {
    int i = blockIdx.x * blockDim.x + threadIdx.x;
    if (i >= n4) return;
    float4 v = x[i];
    __nv_bfloat16 h0 = __float2bfloat16(v.x), h1 = __float2bfloat16(v.y);
    __nv_bfloat16 h2 = __float2bfloat16(v.z), h3 = __float2bfloat16(v.w);
    hi[2*i]   = __halves2bfloat162(h0, h1);
    hi[2*i+1] = __halves2bfloat162(h2, h3);
    lo[2*i]   = __halves2bfloat162(__float2bfloat16(v.x - __bfloat162float(h0)),
                                   __float2bfloat16(v.y - __bfloat162float(h1)));
    lo[2*i+1] = __halves2bfloat162(__float2bfloat16(v.z - __bfloat162float(h2)),
                                   __float2bfloat16(v.w - __bfloat162float(h3)));
}

// ------------------------- non-GEMM kernels --------------------------------
__global__ void init_k(float* mf, float* mb, float* denf, float* denb, float* cols) {
    int i = blockIdx.x*blockDim.x + threadIdx.x;
    if (i < NN) { mf[i] = -INFINITY; mb[i] = -INFINITY; denf[i] = 0.f; denb[i] = 0.f; }
    if (i < 8*FF) cols[i] = 0.f;
}

__global__ void zero4_k(float4* p, int n4) {
    int i = blockIdx.x*blockDim.x + threadIdx.x;
    if (i < n4) p[i] = make_float4(0.f,0.f,0.f,0.f);
}

__global__ void logits_stats_k(
    const float* __restrict__ etmp, const float* __restrict__ af, const float* __restrict__ ab,
    const int* __restrict__ src, const int* __restrict__ dst,
    float* __restrict__ logf, float* __restrict__ logb,
    float* __restrict__ mf, float* __restrict__ mb,
    float* __restrict__ colsum, float* __restrict__ colsumsq)
{
    const int lane = threadIdx.x & 31;
    const int warp = (blockIdx.x*blockDim.x + threadIdx.x) >> 5;
    const int nwarps = (gridDim.x*blockDim.x) >> 5;
    const float4* et4 = (const float4*)etmp;
    const float4 af0 = ((const float4*)af)[lane], af1 = ((const float4*)af)[lane+32];
    const float4 ab0 = ((const float4*)ab)[lane], ab1 = ((const float4*)ab)[lane+32];
    float4 cs0 = make_float4(0,0,0,0), cs1 = cs0, cq0 = cs0, cq1 = cs0;

    for (int r = warp; r < EE; r += nwarps) {
        float4 v0 = et4[r*64 + lane];
        float4 v1 = et4[r*64 + 32 + lane];
        float df = v0.x*af0.x + v0.y*af0.y + v0.z*af0.z + v0.w*af0.w
                 + v1.x*af1.x + v1.y*af1.y + v1.z*af1.z + v1.w*af1.w;
        float db = v0.x*ab0.x + v0.y*ab0.y + v0.z*ab0.z + v0.w*ab0.w
                 + v1.x*ab1.x + v1.y*ab1.y + v1.z*ab1.z + v1.w*ab1.w;
        cs0.x += v0.x; cs0.y += v0.y; cs0.z += v0.z; cs0.w += v0.w;
        cs1.x += v1.x; cs1.y += v1.y; cs1.z += v1.z; cs1.w += v1.w;
        cq0.x += v0.x*v0.x; cq0.y += v0.y*v0.y; cq0.z += v0.z*v0.z; cq0.w += v0.w*v0.w;
        cq1.x += v1.x*v1.x; cq1.y += v1.y*v1.y; cq1.z += v1.z*v1.z; cq1.w += v1.w*v1.w;
        #pragma unroll
        for (int off = 16; off > 0; off >>= 1) {
            df += __shfl_xor_sync(0xFFFFFFFFu, df, off);
            db += __shfl_xor_sync(0xFFFFFFFFu, db, off);
        }
        if (lane == 0) {
            float lf = df > 0.f ? df : 0.2f*df;
            float lb = db > 0.f ? db : 0.2f*db;
            logf[r] = lf; logb[r] = lb;
            atomicMaxF(&mf[dst[r]], lf);
            atomicMaxF(&mb[src[r]], lb);
        }
    }
    int c0 = lane*4, c1 = 128 + lane*4;
    atomicAdd(&colsum[c0+0], cs0.x); atomicAdd(&colsum[c0+1], cs0.y);
    atomicAdd(&colsum[c0+2], cs0.z); atomicAdd(&colsum[c0+3], cs0.w);
    atomicAdd(&colsum[c1+0], cs1.x); atomicAdd(&colsum[c1+1], cs1.y);
    atomicAdd(&colsum[c1+2], cs1.z); atomicAdd(&colsum[c1+3], cs1.w);
    atomicAdd(&colsumsq[c0+0], cq0.x); atomicAdd(&colsumsq[c0+1], cq0.y);
    atomicAdd(&colsumsq[c0+2], cq0.z); atomicAdd(&colsumsq[c0+3], cq0.w);
    atomicAdd(&colsumsq[c1+0], cq1.x); atomicAdd(&colsumsq[c1+1], cq1.y);
    atomicAdd(&colsumsq[c1+2], cq1.z); atomicAdd(&colsumsq[c1+3], cq1.w);
}

__global__ void finalize_bn_k(const float* __restrict__ colsum, const float* __restrict__ colsumsq,
                              const float* __restrict__ g, const float* __restrict__ b,
                              float invM, float* __restrict__ scale, float* __restrict__ shift) {
    int f = threadIdx.x;
    float mean = colsum[f] * invM;
    float var  = colsumsq[f] * invM - mean*mean;
    float sc   = g[f] * rsqrtf(var + 1e-5f);
    scale[f] = sc;
    shift[f] = b[f] - mean * sc;
}

__global__ void exp_k(const float* __restrict__ logf, const float* __restrict__ logb,
                      const int* __restrict__ src, const int* __restrict__ dst,
                      const float* __restrict__ mf, const float* __restrict__ mb,
                      float* __restrict__ exf, float* __restrict__ exb,
                      float* __restrict__ denf, float* __restrict__ denb) {
    int i = blockIdx.x*blockDim.x + threadIdx.x;
    if (i >= EE) return;
    int d = dst[i], s = src[i];
    float ef = expf(logf[i] - mf[d]);
    float eb = expf(logb[i] - mb[s]);
    exf[i] = ef; exb[i] = eb;
    atomicAdd(&denf[d], ef);
    atomicAdd(&denb[s], eb);
}

__global__ void residual_bn_k(const float* __restrict__ base, const float* __restrict__ x,
                              const float* __restrict__ scale, const float* __restrict__ shift,
                              float* __restrict__ out, int n4) {
    int i = blockIdx.x*blockDim.x + threadIdx.x;
    if (i >= n4) return;
    int c4 = i & 63;
    float4 v  = ((const float4*)x)[i];
    float4 bs = ((const float4*)base)[i];
    float4 sc = ((const float4*)scale)[c4];
    float4 sh = ((const float4*)shift)[c4];
    float4 r;
    r.x = bs.x + fmaxf(v.x*sc.x + sh.x, 0.f);
    r.y = bs.y + fmaxf(v.y*sc.y + sh.y, 0.f);
    r.z = bs.z + fmaxf(v.z*sc.z + sh.z, 0.f);
    r.w = bs.w + fmaxf(v.w*sc.w + sh.w, 0.f);
    ((float4*)out)[i] = r;
}

__global__ void aggregate_k(const float* __restrict__ exf, const float* __restrict__ denf,
                            const float* __restrict__ exb, const float* __restrict__ denb,
                            const int* __restrict__ src, const int* __restrict__ dst,
                            const float4* __restrict__ hWf, const float4* __restrict__ hWb,
                            float* __restrict__ aggf, float* __restrict__ aggb) {
    int idx = blockIdx.x*blockDim.x + threadIdx.x;
    int e = idx >> 6, c = idx & 63;
    int s = src[e], d = dst[e];
    float af = exf[e] / (denf[d] + 1e-9f);
    float ab = exb[e] / (denb[s] + 1e-9f);
    float4 vf = hWf[s*64 + c];
    float4 vb = hWb[d*64 + c];
    float* pf = aggf + (d*64 + c)*4;
    float* pb = aggb + (s*64 + c)*4;
    atomicAdd(pf+0, vf.x*af); atomicAdd(pf+1, vf.y*af);
    atomicAdd(pf+2, vf.z*af); atomicAdd(pf+3, vf.w*af);
    atomicAdd(pb+0, vb.x*ab); atomicAdd(pb+1, vb.y*ab);
    atomicAdd(pb+2, vb.z*ab); atomicAdd(pb+3, vb.w*ab);
}

__global__ void node_stats_k(const float* __restrict__ hself, const float* __restrict__ aggf,
                             const float* __restrict__ aggb, float* __restrict__ htmp,
                             float* __restrict__ colsum, float* __restrict__ colsumsq) {
    int c = threadIdx.x;
    int r0 = blockIdx.x * 256;
    int r1 = min(r0 + 256, NN);
    float s = 0.f, q = 0.f;
    for (int r = r0; r < r1; r++) {
        int idx = r*256 + c;
        float v = hself[idx] + aggf[idx] + aggb[idx];
        htmp[idx] = v;
        s += v; q += v*v;
    }
    atomicAdd(&colsum[c], s);
    atomicAdd(&colsumsq[c], q);
}

// ------------------------- host orchestration ------------------------------
static float* symAddrF(const void* sym) { void* p = nullptr; cudaGetSymbolAddress(&p, sym); return (float*)p; }
static __nv_bfloat16* symAddrB(const void* sym) { void* p = nullptr; cudaGetSymbolAddress(&p, sym); return (__nv_bfloat16*)p; }

extern "C" void kernel_launch(void* const* d_in, const int* in_sizes, int n_in,
                              void* d_out, int out_size) {
    const float* h0   = (const float*)d_in[0];
    const float* e0   = (const float*)d_in[1];
    const int*   src  = (const int*)d_in[2];
    const int*   dst  = (const int*)d_in[3];
    const float* We   = (const float*)d_in[4];
    const float* Ws   = (const float*)d_in[5];
    const float* Wd   = (const float*)d_in[6];
    const float* Wse  = (const float*)d_in[7];
    const float* Wf   = (const float*)d_in[8];
    const float* Wb   = (const float*)d_in[9];
    const float* attf = (const float*)d_in[10];
    const float* attb = (const float*)d_in[11];
    const float* ge   = (const float*)d_in[12];
    const float* be   = (const float*)d_in[13];
    const float* gh   = (const float*)d_in[14];
    const float* bh   = (const float*)d_in[15];

    float* eA   = symAddrF(g_eA);
    float* eB   = symAddrF(g_eB);
    float* etmp = symAddrF(g_etmp);
    float* hA   = symAddrF(g_hA);
    float* hB   = symAddrF(g_hB);
    float* hW   = symAddrF(g_hW);
    float* agg  = symAddrF(g_agg);
    float* htmp = symAddrF(g_htmp);
    float* logf = symAddrF(g_logf);
    float* logb = symAddrF(g_logb);
    float* exf  = symAddrF(g_exf);
    float* exb  = symAddrF(g_exb);
    float* mf   = symAddrF(g_mf);
    float* mb   = symAddrF(g_mb);
    float* denf = symAddrF(g_denf);
    float* denb = symAddrF(g_denb);
    float* cols = symAddrF(g_cols);
    __nv_bfloat16* hhi = symAddrB(g_hhi);
    __nv_bfloat16* hlo = symAddrB(g_hlo);
    __nv_bfloat16* ehi = symAddrB(g_ehi);
    __nv_bfloat16* elo = symAddrB(g_elo);
    __nv_bfloat16* Wt  = symAddrB(g_Wt);

    float* hWs = hW;           float* hWd = hW + NF;
    float* hse = hW + 2*NF;    float* hWf_ = hW + 3*NF;
    float* hWb_ = hW + 4*NF;
    float* aggf = agg;         float* aggb = agg + NF;

    float* cse = cols;         float* cqe = cols + FF;
    float* sce = cols + 2*FF;  float* she = cols + 3*FF;
    float* csh = cols + 4*FF;  float* cqh = cols + 5*FF;
    float* sch = cols + 6*FF;  float* shh = cols + 7*FF;

    float* outH; float* outE;
    if (out_size >= NF + EF)      { outH = (float*)d_out; outE = (float*)d_out + NF; }
    else if (out_size == EF)      { outE = (float*)d_out; outH = hB; }
    else                          { outH = (float*)d_out; outE = eB; }

    cudaFuncSetAttribute(node_mma_k, cudaFuncAttributeMaxDynamicSharedMemorySize, SMEMB);
    cudaFuncSetAttribute(edge_mma_k, cudaFuncAttributeMaxDynamicSharedMemorySize, SMEMB);

    // --- transposed + hi/lo-split weights (all layers, all 6 matrices) ---
    W6 w6; w6.p[0] = We; w6.p[1] = Ws; w6.p[2] = Wd; w6.p[3] = Wse; w6.p[4] = Wf; w6.p[5] = Wb;
    prep_w_k<<<(LL*6*WSZ)/256, 256>>>(w6, Wt);

    const float* hin = h0;
    const float* ein = e0;

    for (int l = 0; l < LL; l++) {
        __nv_bfloat16* WtL = Wt + (size_t)l * 6 * WSZ;
        const float* af_l = attf + l*FF;
        const float* ab_l = attb + l*FF;

        float* hout; float* eout;
        if (l == LL-1)      { hout = outH; eout = outE; }
        else if (l & 1)     { hout = hB;   eout = eB;   }
        else                { hout = hA;   eout = eA;   }

        init_k<<<(NN + 255)/256, 256>>>(mf, mb, denf, denb, cols);
        zero4_k<<<(2*NF/4 + 255)/256, 256>>>((float4*)agg, 2*NF/4);

        // fp32 -> bf16 hi/lo splits
        cvt_k<<<(NF/4)/256, 256>>>((const float4*)hin, (__nv_bfloat162*)hhi, (__nv_bfloat162*)hlo, NF/4);
        cvt_k<<<(EF/4)/256, 256>>>((const float4*)ein, (__nv_bfloat162*)ehi, (__nv_bfloat162*)elo, EF/4);

        // node GEMMs: h @ {Ws, Wd, Wself, Wf, Wb}
        O5 p; p.O[0] = hWs; p.O[1] = hWd; p.O[2] = hse; p.O[3] = hWf_; p.O[4] = hWb_;
        node_mma_k<<<dim3((NN + BM - 1)/BM, 1, 5), 256, SMEMB>>>(hhi, hlo, WtL, p, NN);

        // edge GEMM: e_tmp = e @ We + hWs[src] + hWd[dst]
        edge_mma_k<<<EE/BM, 256, SMEMB>>>(ehi, elo, WtL, etmp, src, dst, hWs, hWd);

        logits_stats_k<<<296, 256>>>(etmp, af_l, ab_l, src, dst,
                                     logf, logb, mf, mb, cse, cqe);

        finalize_bn_k<<<1, 256>>>(cse, cqe, ge + l*FF, be + l*FF, 1.0f/EE, sce, she);
        exp_k<<<(EE + 255)/256, 256>>>(logf, logb, src, dst, mf, mb, exf, exb, denf, denb);

        residual_bn_k<<<(EE*64 + 255)/256, 256>>>(ein, etmp, sce, she, eout, EE*64);

        aggregate_k<<<EE*64/256, 256>>>(exf, denf, exb, denb, src, dst,
                                        (const float4*)hWf_, (const float4*)hWb_, aggf, aggb);

        node_stats_k<<<(NN + 255)/256, 256>>>(hse, aggf, aggb, htmp, csh, cqh);
        finalize_bn_k<<<1, 256>>>(csh, cqh, gh + l*FF, bh + l*FF, 1.0f/NN, sch, shh);

        residual_bn_k<<<(NN*64 + 255)/256, 256>>>(hin, htmp, sch, shh, hout, NN*64);

        hin = hout;
        ein = eout;
    }
}

// round 6
// speedup vs baseline: 2.2040x; 1.4933x over previous
#include <cuda_runtime.h>
#include <cuda_bf16.h>
#include <math.h>
#include <stdint.h>

#define NN 50000
#define EE 800000
#define FF 256
#define NF (NN*FF)            // 12,800,000
#define EF (EE*FF)            // 204,800,000
#define LL 4
#define WK 512                // weight K layout: [Whi(256) ; Wlo(256)]
#define WSZ (256*WK)

// GEMM tiling: BM=128, BN=256, BK=64, 512 threads (16 warps, 4x4)
#define BM 128
#define AST 72
#define BST 72
#define ABYTES (BM*AST*2)      // 18432
#define BBYTES (256*BST*2)     // 36864
#define BUFB (ABYTES + BBYTES) // 55296
#define SMEMB (2*BUFB)         // 110592

// ------------------------- scratch (device globals, no allocs) -------------
__device__ float g_etmp[EF];
__device__ float g_hW[5*NF];     // hWs | hWd | hself | hWf | hWb
__device__ float g_htmp[NF];
__device__ float g_logf[EE];
__device__ float g_logb[EE];
__device__ float g_exf[EE];
__device__ float g_exb[EE];
__device__ float g_mf[NN];
__device__ float g_mb[NN];
__device__ float g_denf[NN];
__device__ float g_denb[NN];
__device__ float g_cols[8*FF];
__device__ __nv_bfloat16 g_hhi[NF];
__device__ __nv_bfloat16 g_hlo[NF];
__device__ __nv_bfloat16 g_ehi[EF];
__device__ __nv_bfloat16 g_elo[EF];
__device__ __nv_bfloat16 g_Wt[LL*6*WSZ];
// CSR
__device__ int g_degf[NN];
__device__ int g_degb[NN];
__device__ int g_offf[NN+1];
__device__ int g_offb[NN+1];
__device__ int g_idxf[EE];
__device__ int g_idxb[EE];

// ------------------------- helpers -----------------------------------------
__device__ __forceinline__ uint32_t s2u(const void* p) {
    uint32_t a;
    asm("{ .reg .u64 t; cvta.to.shared.u64 t, %1; cvt.u32.u64 %0, t; }" : "=r"(a) : "l"(p));
    return a;
}
__device__ __forceinline__ void cp_async16(uint32_t saddr, const void* g) {
    asm volatile("cp.async.cg.shared.global [%0], [%1], 16;" :: "r"(saddr), "l"(g));
}
__device__ __forceinline__ void ldsm4(uint32_t addr, uint32_t& r0, uint32_t& r1,
                                      uint32_t& r2, uint32_t& r3) {
    asm volatile("ldmatrix.sync.aligned.m8n8.x4.shared.b16 {%0,%1,%2,%3}, [%4];"
                 : "=r"(r0), "=r"(r1), "=r"(r2), "=r"(r3) : "r"(addr));
}
__device__ __forceinline__ void mma16816(float* d, const uint32_t* a, const uint32_t* b) {
    asm volatile(
        "mma.sync.aligned.m16n8k16.row.col.f32.bf16.bf16.f32 "
        "{%0,%1,%2,%3}, {%4,%5,%6,%7}, {%8,%9}, {%0,%1,%2,%3};"
        : "+f"(d[0]), "+f"(d[1]), "+f"(d[2]), "+f"(d[3])
        : "r"(a[0]), "r"(a[1]), "r"(a[2]), "r"(a[3]), "r"(b[0]), "r"(b[1]));
}
__device__ __forceinline__ void atomicMaxF(float* a, float v) {
    int* ai = (int*)a;
    int old = __float_as_int(*a);
    while (__int_as_float(old) < v) {
        int prev = atomicCAS(ai, old, __float_as_int(v));
        if (prev == old) break;
        old = prev;
    }
}

// ------------------------- bf16 mma GEMM ------------------------------------
// C[tile*128..+128, 0..256) = A@W, 3-term hi/lo split over 12 chunks:
// chunk c: g=c/3, t=c%3; A = (t==1?lo:hi) cols g*64; B rows = (t==2?256:0)+g*64.
// EDGE: adds gs[src]+gd[dst] in epilogue, then computes attention logits
// (+segment max) and BN column stats in-register (fused).
template<bool EDGE>
__device__ __forceinline__ void mma_gemm(
    const __nv_bfloat16* __restrict__ Ahi, const __nv_bfloat16* __restrict__ Alo,
    const __nv_bfloat16* __restrict__ Bt, float* __restrict__ C, int M, int tile,
    const int* __restrict__ src, const int* __restrict__ dst,
    const float* __restrict__ gs, const float* __restrict__ gd,
    const float* __restrict__ af, const float* __restrict__ ab,
    float* __restrict__ logf, float* __restrict__ logb,
    float* __restrict__ mf, float* __restrict__ mb,
    float* __restrict__ cse, float* __restrict__ cqe)
{
    extern __shared__ __align__(16) char smem[];
    const uint32_t sb = s2u(smem);
    const int tid = threadIdx.x, wid = tid >> 5, lane = tid & 31;
    const int m0 = tile * BM;

    auto load_chunk = [&](int c, int buf) {
        int g = c / 3; int t = c - 3*g;
        const __nv_bfloat16* As = (t == 1) ? Alo : Ahi;
        const int acol = g << 6;
        const int kb = ((t == 2) ? 256 : 0) + (g << 6);
        const uint32_t a_s = sb + buf*BUFB;
        const uint32_t b_s = a_s + ABYTES;
        #pragma unroll
        for (int i = 0; i < 2; i++) {            // A: 128x64 halves = 1024 uint4
            int v = tid + (i << 9); int r = v >> 3, c16 = v & 7;
            uint32_t sa = a_s + (r*AST + (c16 << 3))*2;
            int gr = m0 + r;
            if (gr < M) cp_async16(sa, As + (size_t)gr*256 + acol + (c16 << 3));
            else asm volatile("st.shared.v4.b32 [%0], {%1,%1,%1,%1};" :: "r"(sa), "r"(0));
        }
        #pragma unroll
        for (int i = 0; i < 4; i++) {            // B: 256x64 halves = 2048 uint4
            int v = tid + (i << 9); int r = v >> 3, c16 = v & 7;
            cp_async16(b_s + (r*BST + (c16 << 3))*2, Bt + r*WK + kb + (c16 << 3));
        }
        asm volatile("cp.async.commit_group;");
    };

    const int wm = (wid & 3) << 5;               // 0..96
    const int wn = (wid >> 2) << 6;              // 0,64,128,192
    uint32_t a_off[2];
    #pragma unroll
    for (int im = 0; im < 2; im++)
        a_off[im] = ((wm + im*16 + (lane & 15))*AST + ((lane >> 4) << 3))*2;
    const uint32_t b_off = ((wn + ((lane >> 4) << 3) + (lane & 7))*BST
                           + (((lane >> 3) & 1) << 3))*2;

    float acc[2][8][4];
    #pragma unroll
    for (int im = 0; im < 2; im++)
        #pragma unroll
        for (int j = 0; j < 8; j++)
            #pragma unroll
            for (int q = 0; q < 4; q++) acc[im][j][q] = 0.f;

    load_chunk(0, 0);
    int buf = 0;
    for (int c = 0; c < 12; c++) {
        if (c < 11) {
            load_chunk(c + 1, buf ^ 1);
            asm volatile("cp.async.wait_group 1;");
        } else {
            asm volatile("cp.async.wait_group 0;");
        }
        __syncthreads();
        const uint32_t a_s = sb + buf*BUFB;
        const uint32_t b_s = a_s + ABYTES;
        #pragma unroll
        for (int ks = 0; ks < 4; ks++) {
            const uint32_t kh2 = (ks << 4)*2;
            uint32_t a[2][4], b[8][2];
            ldsm4(a_s + a_off[0] + kh2, a[0][0], a[0][1], a[0][2], a[0][3]);
            ldsm4(a_s + a_off[1] + kh2, a[1][0], a[1][1], a[1][2], a[1][3]);
            #pragma unroll
            for (int jp = 0; jp < 4; jp++)
                ldsm4(b_s + b_off + jp*(16*BST*2) + kh2,
                      b[2*jp][0], b[2*jp][1], b[2*jp+1][0], b[2*jp+1][1]);
            #pragma unroll
            for (int im = 0; im < 2; im++)
                #pragma unroll
                for (int j = 0; j < 8; j++)
                    mma16816(acc[im][j], a[im], b[j]);
        }
        __syncthreads();
        buf ^= 1;
    }

    // ---------------- epilogue ----------------
    const int gr0 = lane >> 2;
    const int cl0 = (lane & 3) << 1;

    if (!EDGE) {
        #pragma unroll
        for (int im = 0; im < 2; im++)
            #pragma unroll
            for (int half = 0; half < 2; half++) {
                int gm = m0 + wm + im*16 + gr0 + half*8;
                if (gm >= M) continue;
                #pragma unroll
                for (int j = 0; j < 8; j++) {
                    int col = wn + (j << 3) + cl0;
                    *(float2*)(C + (size_t)gm*256 + col) =
                        make_float2(acc[im][j][half*2], acc[im][j][half*2+1]);
                }
            }
        return;
    }

    // EDGE: fused gather + logits + BN stats
    float* sred = (float*)smem;   // [0:128) rowf | [128:256) rowb | [256:512) cs | [512:768) cq
    for (int i = tid; i < 768; i += 512) sred[i] = 0.f;
    __syncthreads();

    float cs[16], cq[16];
    #pragma unroll
    for (int q = 0; q < 16; q++) { cs[q] = 0.f; cq[q] = 0.f; }

    #pragma unroll
    for (int im = 0; im < 2; im++)
        #pragma unroll
        for (int half = 0; half < 2; half++) {
            int rloc = wm + im*16 + gr0 + half*8;
            int gm = m0 + rloc;
            int s = src[gm], d = dst[gm];
            float pf = 0.f, pb = 0.f;
            #pragma unroll
            for (int j = 0; j < 8; j++) {
                int col = wn + (j << 3) + cl0;
                float2 o = make_float2(acc[im][j][half*2], acc[im][j][half*2+1]);
                float2 x = *(const float2*)(gs + (size_t)s*256 + col);
                float2 y = *(const float2*)(gd + (size_t)d*256 + col);
                o.x += x.x + y.x; o.y += x.y + y.y;
                *(float2*)(C + (size_t)gm*256 + col) = o;
                pf += o.x*__ldg(af+col) + o.y*__ldg(af+col+1);
                pb += o.x*__ldg(ab+col) + o.y*__ldg(ab+col+1);
                cs[j*2]   += o.x; cs[j*2+1] += o.y;
                cq[j*2]   += o.x*o.x; cq[j*2+1] += o.y*o.y;
            }
            pf += __shfl_xor_sync(0xFFFFFFFFu, pf, 1);
            pf += __shfl_xor_sync(0xFFFFFFFFu, pf, 2);
            pb += __shfl_xor_sync(0xFFFFFFFFu, pb, 1);
            pb += __shfl_xor_sync(0xFFFFFFFFu, pb, 2);
            if ((lane & 3) == 0) {
                atomicAdd(&sred[rloc], pf);
                atomicAdd(&sred[128 + rloc], pb);
            }
        }
    #pragma unroll
    for (int q = 0; q < 16; q++) {
        cs[q] += __shfl_xor_sync(0xFFFFFFFFu, cs[q], 4);
        cs[q] += __shfl_xor_sync(0xFFFFFFFFu, cs[q], 8);
        cs[q] += __shfl_xor_sync(0xFFFFFFFFu, cs[q], 16);
        cq[q] += __shfl_xor_sync(0xFFFFFFFFu, cq[q], 4);
        cq[q] += __shfl_xor_sync(0xFFFFFFFFu, cq[q], 8);
        cq[q] += __shfl_xor_sync(0xFFFFFFFFu, cq[q], 16);
    }
    if (lane < 4) {
        #pragma unroll
        for (int j = 0; j < 8; j++) {
            int col = wn + (j << 3) + ((lane & 3) << 1);
            atomicAdd(&sred[256 + col],     cs[j*2]);
            atomicAdd(&sred[256 + col + 1], cs[j*2+1]);
            atomicAdd(&sred[512 + col],     cq[j*2]);
            atomicAdd(&sred[512 + col + 1], cq[j*2+1]);
        }
    }
    __syncthreads();
    if (tid < 128) {
        int gm = m0 + tid;
        float lf = sred[tid];       lf = lf > 0.f ? lf : 0.2f*lf;
        float lb = sred[128 + tid]; lb = lb > 0.f ? lb : 0.2f*lb;
        logf[gm] = lf; logb[gm] = lb;
        atomicMaxF(&mf[dst[gm]], lf);
        atomicMaxF(&mb[src[gm]], lb);
    } else if (tid < 384) {
        int col = tid - 128;
        atomicAdd(&cse[col], sred[256 + col]);
        atomicAdd(&cqe[col], sred[512 + col]);
    }
}

struct O5 { float* O[5]; };

__global__ __launch_bounds__(512)
void node_mma_k(const __nv_bfloat16* __restrict__ Ahi, const __nv_bfloat16* __restrict__ Alo,
                const __nv_bfloat16* __restrict__ WtL, O5 p, int M) {
    mma_gemm<false>(Ahi, Alo, WtL + (size_t)(blockIdx.z + 1)*WSZ, p.O[blockIdx.z],
                    M, blockIdx.x, nullptr, nullptr, nullptr, nullptr,
                    nullptr, nullptr, nullptr, nullptr, nullptr, nullptr, nullptr, nullptr);
}

__global__ __launch_bounds__(512)
void edge_mma_k(const __nv_bfloat16* __restrict__ Ahi, const __nv_bfloat16* __restrict__ Alo,
                const __nv_bfloat16* __restrict__ WtL, float* __restrict__ C,
                const int* __restrict__ src, const int* __restrict__ dst,
                const float* __restrict__ gs, const float* __restrict__ gd,
                const float* __restrict__ af, const float* __restrict__ ab,
                float* __restrict__ logf, float* __restrict__ logb,
                float* __restrict__ mf, float* __restrict__ mb,
                float* __restrict__ cse, float* __restrict__ cqe) {
    mma_gemm<true>(Ahi, Alo, WtL, C, EE, blockIdx.x, src, dst, gs, gd,
                   af, ab, logf, logb, mf, mb, cse, cqe);
}

// ------------------------- prep / CSR ---------------------------------------
struct W6 { const float* p[6]; };

__global__ void prep_w_k(W6 w, __nv_bfloat16* __restrict__ out) {
    long idx = (long)blockIdx.x * 256 + threadIdx.x;      // LL*6*256*512
    int k = (int)(idx % WK); long t = idx / WK;
    int n = (int)(t % 256);  t /= 256;
    int wi = (int)(t % 6);   int l = (int)(t / 6);
    int k2 = k & 255;
    float v = w.p[wi][((size_t)l * 256 + k2) * 256 + n];
    __nv_bfloat16 h = __float2bfloat16(v);
    out[idx] = (k < 256) ? h : __float2bfloat16(v - __bfloat162float(h));
}

__global__ void cvt_k(const float4* __restrict__ x, __nv_bfloat162* __restrict__ hi,
                      __nv_bfloat162* __restrict__ lo, int n4) {
    int i = blockIdx.x * blockDim.x + threadIdx.x;
    if (i >= n4) return;
    float4 v = x[i];
    __nv_bfloat16 h0 = __float2bfloat16(v.x), h1 = __float2bfloat16(v.y);
    __nv_bfloat16 h2 = __float2bfloat16(v.z), h3 = __float2bfloat16(v.w);
    hi[2*i]   = __halves2bfloat162(h0, h1);
    hi[2*i+1] = __halves2bfloat162(h2, h3);
    lo[2*i]   = __halves2bfloat162(__float2bfloat16(v.x - __bfloat162float(h0)),
                                   __float2bfloat16(v.y - __bfloat162float(h1)));
    lo[2*i+1] = __halves2bfloat162(__float2bfloat16(v.z - __bfloat162float(h2)),
                                   __float2bfloat16(v.w - __bfloat162float(h3)));
}

__global__ void zero_deg_k(int* df, int* db) {
    int i = blockIdx.x*blockDim.x + threadIdx.x;
    if (i < NN) { df[i] = 0; db[i] = 0; }
}
__global__ void hist_k(const int* __restrict__ src, const int* __restrict__ dst,
                       int* df, int* db) {
    int e = blockIdx.x*blockDim.x + threadIdx.x;
    if (e >= EE) return;
    atomicAdd(&df[dst[e]], 1);
    atomicAdd(&db[src[e]], 1);
}
__global__ void scan_k(const int* __restrict__ degf, const int* __restrict__ degb,
                       int* offf, int* offb) {
    __shared__ int s[1024];
    for (int arr = 0; arr < 2; arr++) {
        const int* deg = arr ? degb : degf;
        int* off = arr ? offb : offf;
        int carry = 0;
        if (threadIdx.x == 0) off[0] = 0;
        for (int base = 0; base < NN; base += 1024) {
            int i = base + threadIdx.x;
            s[threadIdx.x] = (i < NN) ? deg[i] : 0;
            __syncthreads();
            for (int d = 1; d < 1024; d <<= 1) {
                int t = (threadIdx.x >= d) ? s[threadIdx.x - d] : 0;
                __syncthreads();
                s[threadIdx.x] += t;
                __syncthreads();
            }
            if (i < NN) off[i+1] = carry + s[threadIdx.x];
            carry += s[1023];
            __syncthreads();
        }
    }
}
__global__ void curcpy_k(const int* offf, const int* offb, int* curf, int* curb) {
    int i = blockIdx.x*blockDim.x + threadIdx.x;
    if (i < NN) { curf[i] = offf[i]; curb[i] = offb[i]; }
}
__global__ void fill_k(const int* __restrict__ src, const int* __restrict__ dst,
                       int* curf, int* curb, int* idxf, int* idxb) {
    int e = blockIdx.x*blockDim.x + threadIdx.x;
    if (e >= EE) return;
    idxf[atomicAdd(&curf[dst[e]], 1)] = e;
    idxb[atomicAdd(&curb[src[e]], 1)] = e;
}

// ------------------------- per-layer small kernels --------------------------
__global__ void init_k(float* mf, float* mb, float* denf, float* denb, float* cols) {
    int i = blockIdx.x*blockDim.x + threadIdx.x;
    if (i < NN) { mf[i] = -INFINITY; mb[i] = -INFINITY; denf[i] = 0.f; denb[i] = 0.f; }
    if (i < 8*FF) cols[i] = 0.f;
}

__global__ void finalize_bn_k(const float* __restrict__ colsum, const float* __restrict__ colsumsq,
                              const float* __restrict__ g, const float* __restrict__ b,
                              float invM, float* __restrict__ scale, float* __restrict__ shift) {
    int f = threadIdx.x;
    float mean = colsum[f] * invM;
    float var  = colsumsq[f] * invM - mean*mean;
    float sc   = g[f] * rsqrtf(var + 1e-5f);
    scale[f] = sc;
    shift[f] = b[f] - mean * sc;
}

__global__ void exp_k(const float* __restrict__ logf, const float* __restrict__ logb,
                      const int* __restrict__ src, const int* __restrict__ dst,
                      const float* __restrict__ mf, const float* __restrict__ mb,
                      float* __restrict__ exf, float* __restrict__ exb,
                      float* __restrict__ denf, float* __restrict__ denb) {
    int i = blockIdx.x*blockDim.x + threadIdx.x;
    if (i >= EE) return;
    int d = dst[i], s = src[i];
    float ef = expf(logf[i] - mf[d]);
    float eb = expf(logb[i] - mb[s]);
    exf[i] = ef; exb[i] = eb;
    atomicAdd(&denf[d], ef);
    atomicAdd(&denb[s], eb);
}

// out = (hi+lo) + relu(x*scale+shift); store back as hi/lo; optional fp32 out
__global__ void residual_hl_k(__nv_bfloat162* hi, __nv_bfloat162* lo,
                              const float4* __restrict__ x,
                              const float* __restrict__ scale, const float* __restrict__ shift,
                              float4* __restrict__ outF, int n4, int writeF) {
    int i = blockIdx.x*blockDim.x + threadIdx.x;
    if (i >= n4) return;
    int c4 = i & 63;
    __nv_bfloat162 a0 = hi[2*i], a1 = hi[2*i+1], b0 = lo[2*i], b1 = lo[2*i+1];
    float4 base;
    base.x = __bfloat162float(a0.x) + __bfloat162float(b0.x);
    base.y = __bfloat162float(a0.y) + __bfloat162float(b0.y);
    base.z = __bfloat162float(a1.x) + __bfloat162float(b1.x);
    base.w = __bfloat162float(a1.y) + __bfloat162float(b1.y);
    float4 v  = x[i];
    float4 sc = ((const float4*)scale)[c4];
    float4 sh = ((const float4*)shift)[c4];
    float4 r;
    r.x = base.x + fmaxf(v.x*sc.x + sh.x, 0.f);
    r.y = base.y + fmaxf(v.y*sc.y + sh.y, 0.f);
    r.z = base.z + fmaxf(v.z*sc.z + sh.z, 0.f);
    r.w = base.w + fmaxf(v.w*sc.w + sh.w, 0.f);
    __nv_bfloat16 h0 = __float2bfloat16(r.x), h1 = __float2bfloat16(r.y);
    __nv_bfloat16 h2 = __float2bfloat16(r.z), h3 = __float2bfloat16(r.w);
    hi[2*i]   = __halves2bfloat162(h0, h1);
    hi[2*i+1] = __halves2bfloat162(h2, h3);
    lo[2*i]   = __halves2bfloat162(__float2bfloat16(r.x - __bfloat162float(h0)),
                                   __float2bfloat16(r.y - __bfloat162float(h1)));
    lo[2*i+1] = __halves2bfloat162(__float2bfloat16(r.z - __bfloat162float(h2)),
                                   __float2bfloat16(r.w - __bfloat162float(h3)));
    if (writeF) outF[i] = r;
}

// CSR gather aggregation + node update + BN stats. 256 thr: sub=tid>>6 (4), c=tid&63.
// Block handles 32 nodes (sub*8 + nn).
__global__ void gather_node_k(
    const int* __restrict__ offf, const int* __restrict__ idxf,
    const int* __restrict__ offb, const int* __restrict__ idxb,
    const int* __restrict__ src, const int* __restrict__ dst,
    const float* __restrict__ exf, const float* __restrict__ denf,
    const float* __restrict__ exb, const float* __restrict__ denb,
    const float4* __restrict__ hWf, const float4* __restrict__ hWb,
    const float4* __restrict__ hself, float4* __restrict__ htmp,
    float* __restrict__ colsum, float* __restrict__ colsumsq) {
    __shared__ float4 scs[256], scq[256];
    const int sub = threadIdx.x >> 6, c = threadIdx.x & 63;
    float4 csum = make_float4(0,0,0,0), csq = make_float4(0,0,0,0);
    #pragma unroll 1
    for (int nn = 0; nn < 8; nn++) {
        int node = blockIdx.x*32 + sub*8 + nn;
        if (node >= NN) break;
        float invf = 1.f/(denf[node] + 1e-9f);
        float invb = 1.f/(denb[node] + 1e-9f);
        float4 acc = hself[(size_t)node*64 + c];
        int e0 = offf[node], e1 = offf[node+1];
        for (int i = e0; i < e1; i++) {
            int e = idxf[i];
            float a = exf[e]*invf;
            float4 v = hWf[(size_t)src[e]*64 + c];
            acc.x += a*v.x; acc.y += a*v.y; acc.z += a*v.z; acc.w += a*v.w;
        }
        e0 = offb[node]; e1 = offb[node+1];
        for (int i = e0; i < e1; i++) {
            int e = idxb[i];
            float a = exb[e]*invb;
            float4 v = hWb[(size_t)dst[e]*64 + c];
            acc.x += a*v.x; acc.y += a*v.y; acc.z += a*v.z; acc.w += a*v.w;
        }
        htmp[(size_t)node*64 + c] = acc;
        csum.x += acc.x; csum.y += acc.y; csum.z += acc.z; csum.w += acc.w;
        csq.x += acc.x*acc.x; csq.y += acc.y*acc.y; csq.z += acc.z*acc.z; csq.w += acc.w*acc.w;
    }
    scs[threadIdx.x] = csum; scq[threadIdx.x] = csq;
    __syncthreads();
    if (sub == 0) {
        float4 s = scs[c], q = scq[c];
        #pragma unroll
        for (int k = 1; k < 4; k++) {
            float4 t = scs[k*64 + c], u = scq[k*64 + c];
            s.x += t.x; s.y += t.y; s.z += t.z; s.w += t.w;
            q.x += u.x; q.y += u.y; q.z += u.z; q.w += u.w;
        }
        atomicAdd(&colsum[c*4+0], s.x); atomicAdd(&colsum[c*4+1], s.y);
        atomicAdd(&colsum[c*4+2], s.z); atomicAdd(&colsum[c*4+3], s.w);
        atomicAdd(&colsumsq[c*4+0], q.x); atomicAdd(&colsumsq[c*4+1], q.y);
        atomicAdd(&colsumsq[c*4+2], q.z); atomicAdd(&colsumsq[c*4+3], q.w);
    }
}

// ------------------------- host orchestration ------------------------------
static float* symF(const void* s) { void* p = nullptr; cudaGetSymbolAddress(&p, s); return (float*)p; }
static int*   symI(const void* s) { void* p = nullptr; cudaGetSymbolAddress(&p, s); return (int*)p; }
static __nv_bfloat16* symB(const void* s) { void* p = nullptr; cudaGetSymbolAddress(&p, s); return (__nv_bfloat16*)p; }

extern "C" void kernel_launch(void* const* d_in, const int* in_sizes, int n_in,
                              void* d_out, int out_size) {
    const float* h0   = (const float*)d_in[0];
    const float* e0   = (const float*)d_in[1];
    const int*   src  = (const int*)d_in[2];
    const int*   dst  = (const int*)d_in[3];
    const float* We   = (const float*)d_in[4];
    const float* Ws   = (const float*)d_in[5];
    const float* Wd   = (const float*)d_in[6];
    const float* Wse  = (const float*)d_in[7];
    const float* Wf   = (const float*)d_in[8];
    const float* Wb   = (const float*)d_in[9];
    const float* attf = (const float*)d_in[10];
    const float* attb = (const float*)d_in[11];
    const float* ge   = (const float*)d_in[12];
    const float* be   = (const float*)d_in[13];
    const float* gh   = (const float*)d_in[14];
    const float* bh   = (const float*)d_in[15];

    float* etmp = symF(g_etmp);
    float* hW   = symF(g_hW);
    float* htmp = symF(g_htmp);
    float* logf = symF(g_logf);
    float* logb = symF(g_logb);
    float* exf  = symF(g_exf);
    float* exb  = symF(g_exb);
    float* mf   = symF(g_mf);
    float* mb   = symF(g_mb);
    float* denf = symF(g_denf);
    float* denb = symF(g_denb);
    float* cols = symF(g_cols);
    __nv_bfloat16* hhi = symB(g_hhi);
    __nv_bfloat16* hlo = symB(g_hlo);
    __nv_bfloat16* ehi = symB(g_ehi);
    __nv_bfloat16* elo = symB(g_elo);
    __nv_bfloat16* Wt  = symB(g_Wt);
    int* degf = symI(g_degf);  int* degb = symI(g_degb);
    int* offf = symI(g_offf);  int* offb = symI(g_offb);
    int* idxf = symI(g_idxf);  int* idxb = symI(g_idxb);

    float* hWs = hW;           float* hWd = hW + NF;
    float* hse = hW + 2*NF;    float* hWf_ = hW + 3*NF;
    float* hWb_ = hW + 4*NF;

    float* cse = cols;         float* cqe = cols + FF;
    float* sce = cols + 2*FF;  float* she = cols + 3*FF;
    float* csh = cols + 4*FF;  float* cqh = cols + 5*FF;
    float* sch = cols + 6*FF;  float* shh = cols + 7*FF;

    float* outH; float* outE;
    if (out_size >= NF + EF)      { outH = (float*)d_out; outE = (float*)d_out + NF; }
    else if (out_size == EF)      { outE = (float*)d_out; outH = htmp; }
    else                          { outH = (float*)d_out; outE = etmp; }

    cudaFuncSetAttribute(node_mma_k, cudaFuncAttributeMaxDynamicSharedMemorySize, SMEMB);
    cudaFuncSetAttribute(edge_mma_k, cudaFuncAttributeMaxDynamicSharedMemorySize, SMEMB);

    // weights (once)
    W6 w6; w6.p[0] = We; w6.p[1] = Ws; w6.p[2] = Wd; w6.p[3] = Wse; w6.p[4] = Wf; w6.p[5] = Wb;
    prep_w_k<<<(LL*6*WSZ)/256, 256>>>(w6, Wt);

    // inputs -> hi/lo (once)
    cvt_k<<<(NF/4 + 255)/256, 256>>>((const float4*)h0, (__nv_bfloat162*)hhi, (__nv_bfloat162*)hlo, NF/4);
    cvt_k<<<(EF/4 + 255)/256, 256>>>((const float4*)e0, (__nv_bfloat162*)ehi, (__nv_bfloat162*)elo, EF/4);

    // CSR (once per launch)
    zero_deg_k<<<(NN+255)/256, 256>>>(degf, degb);
    hist_k<<<(EE+255)/256, 256>>>(src, dst, degf, degb);
    scan_k<<<1, 1024>>>(degf, degb, offf, offb);
    curcpy_k<<<(NN+255)/256, 256>>>(offf, offb, degf, degb);
    fill_k<<<(EE+255)/256, 256>>>(src, dst, degf, degb, idxf, idxb);

    for (int l = 0; l < LL; l++) {
        __nv_bfloat16* WtL = Wt + (size_t)l * 6 * WSZ;
        int last = (l == LL-1);

        init_k<<<(NN + 255)/256, 256>>>(mf, mb, denf, denb, cols);

        // node GEMMs: h @ {Ws, Wd, Wself, Wf, Wb}
        O5 p; p.O[0] = hWs; p.O[1] = hWd; p.O[2] = hse; p.O[3] = hWf_; p.O[4] = hWb_;
        node_mma_k<<<dim3((NN + BM - 1)/BM, 1, 5), 512, SMEMB>>>(hhi, hlo, WtL, p, NN);

        // edge GEMM + fused gather/logits/max/BN-stats
        edge_mma_k<<<EE/BM, 512, SMEMB>>>(ehi, elo, WtL, etmp, src, dst, hWs, hWd,
                                          attf + l*FF, attb + l*FF,
                                          logf, logb, mf, mb, cse, cqe);

        finalize_bn_k<<<1, 256>>>(cse, cqe, ge + l*FF, be + l*FF, 1.0f/EE, sce, she);
        exp_k<<<(EE + 255)/256, 256>>>(logf, logb, src, dst, mf, mb, exf, exb, denf, denb);

        // e residual (in-place hi/lo, fp32 out on last layer)
        residual_hl_k<<<(EF/4 + 255)/256, 256>>>((__nv_bfloat162*)ehi, (__nv_bfloat162*)elo,
                                                 (const float4*)etmp, sce, she,
                                                 (float4*)outE, EF/4, last);

        // attention aggregation (CSR gather) + node update + BN stats
        gather_node_k<<<(NN + 31)/32, 256>>>(offf, idxf, offb, idxb, src, dst,
                                             exf, denf, exb, denb,
                                             (const float4*)hWf_, (const float4*)hWb_,
                                             (const float4*)hse, (float4*)htmp, csh, cqh);
        finalize_bn_k<<<1, 256>>>(csh, cqh, gh + l*FF, bh + l*FF, 1.0f/NN, sch, shh);

        // h residual (in-place hi/lo, fp32 out on last layer)
        residual_hl_k<<<(NF/4 + 255)/256, 256>>>((__nv_bfloat162*)hhi, (__nv_bfloat162*)hlo,
                                                 (const float4*)htmp, sch, shh,
                                                 (float4*)outH, NF/4, last);
    }
}

// round 8
// speedup vs baseline: 2.6012x; 1.1802x over previous
#include <cuda_runtime.h>
#include <cuda_fp16.h>
#include <math.h>
#include <stdint.h>

#define NN 50000
#define EE 800000
#define FF 256
#define NF (NN*FF)            // 12,800,000
#define EF (EE*FF)            // 204,800,000
#define LL 4
#define WK 256                // weight: single fp16 [N=256, K=256] K-major
#define WSZ (256*WK)
#define NCHUNK 8              // 2-term split: (g,t) g=c>>1 in 0..3, t=c&1 (hi/lo)

// GEMM tiling: BM=128, BN=256, BK=64, 512 threads (16 warps, 4x4)
#define BM 128
#define AST 72
#define BST 72
#define ABYTES (BM*AST*2)      // 18432
#define BBYTES (256*BST*2)     // 36864
#define BUFB (ABYTES + BBYTES) // 55296
#define SMEMB (2*BUFB)         // 110592

// ------------------------- scratch (device globals, no allocs) -------------
__device__ float g_etmp[EF];
__device__ float g_hW[5*NF];     // hWs | hWd | hself | hWf | hWb
__device__ float g_htmp[NF];
__device__ float g_logf[EE];
__device__ float g_logb[EE];
__device__ float g_exf[EE];
__device__ float g_exb[EE];
__device__ float g_mf[NN];
__device__ float g_mb[NN];
__device__ float g_denf[NN];
__device__ float g_denb[NN];
__device__ float g_cols[8*FF];
__device__ __half g_hhi[NF];
__device__ __half g_hlo[NF];
__device__ __half g_ehi[EF];
__device__ __half g_elo[EF];
__device__ __half g_Wt[LL*6*WSZ];
// CSR
__device__ int g_degf[NN];
__device__ int g_degb[NN];
__device__ int g_offf[NN+1];
__device__ int g_offb[NN+1];
__device__ int g_idxf[EE];
__device__ int g_idxb[EE];

// ------------------------- helpers -----------------------------------------
__device__ __forceinline__ uint32_t s2u(const void* p) {
    uint32_t a;
    asm("{ .reg .u64 t; cvta.to.shared.u64 t, %1; cvt.u32.u64 %0, t; }" : "=r"(a) : "l"(p));
    return a;
}
__device__ __forceinline__ void cp_async16(uint32_t saddr, const void* g) {
    asm volatile("cp.async.cg.shared.global [%0], [%1], 16;" :: "r"(saddr), "l"(g));
}
__device__ __forceinline__ void ldsm4(uint32_t addr, uint32_t& r0, uint32_t& r1,
                                      uint32_t& r2, uint32_t& r3) {
    asm volatile("ldmatrix.sync.aligned.m8n8.x4.shared.b16 {%0,%1,%2,%3}, [%4];"
                 : "=r"(r0), "=r"(r1), "=r"(r2), "=r"(r3) : "r"(addr));
}
__device__ __forceinline__ void mma16816(float* d, const uint32_t* a, const uint32_t* b) {
    asm volatile(
        "mma.sync.aligned.m16n8k16.row.col.f32.f16.f16.f32 "
        "{%0,%1,%2,%3}, {%4,%5,%6,%7}, {%8,%9}, {%0,%1,%2,%3};"
        : "+f"(d[0]), "+f"(d[1]), "+f"(d[2]), "+f"(d[3])
        : "r"(a[0]), "r"(a[1]), "r"(a[2]), "r"(a[3]), "r"(b[0]), "r"(b[1]));
}
__device__ __forceinline__ void atomicMaxF(float* a, float v) {
    int* ai = (int*)a;
    int old = __float_as_int(*a);
    while (__int_as_float(old) < v) {
        int prev = atomicCAS(ai, old, __float_as_int(v));
        if (prev == old) break;
        old = prev;
    }
}

// ------------------------- fp16 mma GEMM ------------------------------------
// C[tile*128..+128, 0..256) = A@W, 2-term fp16 hi/lo split over 8 chunks:
// chunk c: g=c>>1, t=c&1; A = (t?lo:hi) cols g*64; B rows = g*64.
// EDGE: adds gs[src]+gd[dst] in epilogue, then attention logits (+segment max)
// and BN column stats in-register (fused).
template<bool EDGE>
__device__ __forceinline__ void mma_gemm(
    const __half* __restrict__ Ahi, const __half* __restrict__ Alo,
    const __half* __restrict__ Bt, float* __restrict__ C, int M, int tile,
    const int* __restrict__ src, const int* __restrict__ dst,
    const float* __restrict__ gs, const float* __restrict__ gd,
    const float* __restrict__ af, const float* __restrict__ ab,
    float* __restrict__ logf, float* __restrict__ logb,
    float* __restrict__ mf, float* __restrict__ mb,
    float* __restrict__ cse, float* __restrict__ cqe)
{
    extern __shared__ __align__(16) char smem[];
    const uint32_t sb = s2u(smem);
    const int tid = threadIdx.x, wid = tid >> 5, lane = tid & 31;
    const int m0 = tile * BM;

    auto load_chunk = [&](int c, int buf) {
        int g = c >> 1, t = c & 1;
        const __half* As = t ? Alo : Ahi;
        const int acol = g << 6;
        const int kb = g << 6;
        const uint32_t a_s = sb + buf*BUFB;
        const uint32_t b_s = a_s + ABYTES;
        #pragma unroll
        for (int i = 0; i < 2; i++) {            // A: 128x64 halves = 1024 uint4
            int v = tid + (i << 9); int r = v >> 3, c16 = v & 7;
            uint32_t sa = a_s + (r*AST + (c16 << 3))*2;
            int gr = m0 + r;
            if (EDGE) {
                cp_async16(sa, As + (size_t)gr*256 + acol + (c16 << 3));
            } else {
                if (gr < M) cp_async16(sa, As + (size_t)gr*256 + acol + (c16 << 3));
                else asm volatile("st.shared.v4.b32 [%0], {%1,%1,%1,%1};" :: "r"(sa), "r"(0));
            }
        }
        #pragma unroll
        for (int i = 0; i < 4; i++) {            // B: 256x64 halves = 2048 uint4
            int v = tid + (i << 9); int r = v >> 3, c16 = v & 7;
            cp_async16(b_s + (r*BST + (c16 << 3))*2, Bt + r*WK + kb + (c16 << 3));
        }
        asm volatile("cp.async.commit_group;");
    };

    const int wm = (wid & 3) << 5;               // 0..96
    const int wn = (wid >> 2) << 6;              // 0,64,128,192
    uint32_t a_off[2];
    #pragma unroll
    for (int im = 0; im < 2; im++)
        a_off[im] = ((wm + im*16 + (lane & 15))*AST + ((lane >> 4) << 3))*2;
    const uint32_t b_off = ((wn + ((lane >> 4) << 3) + (lane & 7))*BST
                           + (((lane >> 3) & 1) << 3))*2;

    float acc[2][8][4];
    #pragma unroll
    for (int im = 0; im < 2; im++)
        #pragma unroll
        for (int j = 0; j < 8; j++)
            #pragma unroll
            for (int q = 0; q < 4; q++) acc[im][j][q] = 0.f;

    load_chunk(0, 0);
    int buf = 0;
    for (int c = 0; c < NCHUNK; c++) {
        if (c < NCHUNK-1) {
            load_chunk(c + 1, buf ^ 1);
            asm volatile("cp.async.wait_group 1;");
        } else {
            asm volatile("cp.async.wait_group 0;");
        }
        __syncthreads();
        const uint32_t a_s = sb + buf*BUFB;
        const uint32_t b_s = a_s + ABYTES;
        #pragma unroll
        for (int ks = 0; ks < 4; ks++) {
            const uint32_t kh2 = (ks << 4)*2;
            uint32_t a[2][4], b[8][2];
            ldsm4(a_s + a_off[0] + kh2, a[0][0], a[0][1], a[0][2], a[0][3]);
            ldsm4(a_s + a_off[1] + kh2, a[1][0], a[1][1], a[1][2], a[1][3]);
            #pragma unroll
            for (int jp = 0; jp < 4; jp++)
                ldsm4(b_s + b_off + jp*(16*BST*2) + kh2,
                      b[2*jp][0], b[2*jp][1], b[2*jp+1][0], b[2*jp+1][1]);
            #pragma unroll
            for (int im = 0; im < 2; im++)
                #pragma unroll
                for (int j = 0; j < 8; j++)
                    mma16816(acc[im][j], a[im], b[j]);
        }
        __syncthreads();
        buf ^= 1;
    }

    // ---------------- epilogue ----------------
    const int gr0 = lane >> 2;
    const int cl0 = (lane & 3) << 1;

    if (!EDGE) {
        #pragma unroll
        for (int im = 0; im < 2; im++)
            #pragma unroll
            for (int half = 0; half < 2; half++) {
                int gm = m0 + wm + im*16 + gr0 + half*8;
                if (gm >= M) continue;
                #pragma unroll
                for (int j = 0; j < 8; j++) {
                    int col = wn + (j << 3) + cl0;
                    *(float2*)(C + (size_t)gm*256 + col) =
                        make_float2(acc[im][j][half*2], acc[im][j][half*2+1]);
                }
            }
        return;
    }

    // EDGE: fused gather + logits + BN stats
    float* sred = (float*)smem;   // [0:128) rowf | [128:256) rowb | [256:512) cs | [512:768) cq
    for (int i = tid; i < 768; i += 512) sred[i] = 0.f;
    __syncthreads();

    float cs[16], cq[16];
    #pragma unroll
    for (int q = 0; q < 16; q++) { cs[q] = 0.f; cq[q] = 0.f; }

    #pragma unroll
    for (int im = 0; im < 2; im++)
        #pragma unroll
        for (int half = 0; half < 2; half++) {
            int rloc = wm + im*16 + gr0 + half*8;
            int gm = m0 + rloc;
            int s = src[gm], d = dst[gm];
            float pf = 0.f, pb = 0.f;
            #pragma unroll
            for (int j = 0; j < 8; j++) {
                int col = wn + (j << 3) + cl0;
                float2 o = make_float2(acc[im][j][half*2], acc[im][j][half*2+1]);
                float2 x = *(const float2*)(gs + (size_t)s*256 + col);
                float2 y = *(const float2*)(gd + (size_t)d*256 + col);
                o.x += x.x + y.x; o.y += x.y + y.y;
                *(float2*)(C + (size_t)gm*256 + col) = o;
                pf += o.x*__ldg(af+col) + o.y*__ldg(af+col+1);
                pb += o.x*__ldg(ab+col) + o.y*__ldg(ab+col+1);
                cs[j*2]   += o.x; cs[j*2+1] += o.y;
                cq[j*2]   += o.x*o.x; cq[j*2+1] += o.y*o.y;
            }
            pf += __shfl_xor_sync(0xFFFFFFFFu, pf, 1);
            pf += __shfl_xor_sync(0xFFFFFFFFu, pf, 2);
            pb += __shfl_xor_sync(0xFFFFFFFFu, pb, 1);
            pb += __shfl_xor_sync(0xFFFFFFFFu, pb, 2);
            if ((lane & 3) == 0) {
                atomicAdd(&sred[rloc], pf);
                atomicAdd(&sred[128 + rloc], pb);
            }
        }
    #pragma unroll
    for (int q = 0; q < 16; q++) {
        cs[q] += __shfl_xor_sync(0xFFFFFFFFu, cs[q], 4);
        cs[q] += __shfl_xor_sync(0xFFFFFFFFu, cs[q], 8);
        cs[q] += __shfl_xor_sync(0xFFFFFFFFu, cs[q], 16);
        cq[q] += __shfl_xor_sync(0xFFFFFFFFu, cq[q], 4);
        cq[q] += __shfl_xor_sync(0xFFFFFFFFu, cq[q], 8);
        cq[q] += __shfl_xor_sync(0xFFFFFFFFu, cq[q], 16);
    }
    if (lane < 4) {
        #pragma unroll
        for (int j = 0; j < 8; j++) {
            int col = wn + (j << 3) + ((lane & 3) << 1);
            atomicAdd(&sred[256 + col],     cs[j*2]);
            atomicAdd(&sred[256 + col + 1], cs[j*2+1]);
            atomicAdd(&sred[512 + col],     cq[j*2]);
            atomicAdd(&sred[512 + col + 1], cq[j*2+1]);
        }
    }
    __syncthreads();
    if (tid < 128) {
        int gm = m0 + tid;
        float lf = sred[tid];       lf = lf > 0.f ? lf : 0.2f*lf;
        float lb = sred[128 + tid]; lb = lb > 0.f ? lb : 0.2f*lb;
        logf[gm] = lf; logb[gm] = lb;
        atomicMaxF(&mf[dst[gm]], lf);
        atomicMaxF(&mb[src[gm]], lb);
    } else if (tid < 384) {
        int col = tid - 128;
        atomicAdd(&cse[col], sred[256 + col]);
        atomicAdd(&cqe[col], sred[512 + col]);
    }
}

struct O5 { float* O[5]; };

__global__ __launch_bounds__(512)
void node_mma_k(const __half* __restrict__ Ahi, const __half* __restrict__ Alo,
                const __half* __restrict__ WtL, O5 p, int M) {
    mma_gemm<false>(Ahi, Alo, WtL + (size_t)(blockIdx.z + 1)*WSZ, p.O[blockIdx.z],
                    M, blockIdx.x, nullptr, nullptr, nullptr, nullptr,
                    nullptr, nullptr, nullptr, nullptr, nullptr, nullptr, nullptr, nullptr);
}

__global__ __launch_bounds__(512)
void edge_mma_k(const __half* __restrict__ Ahi, const __half* __restrict__ Alo,
                const __half* __restrict__ WtL, float* __restrict__ C,
                const int* __restrict__ src, const int* __restrict__ dst,
                const float* __restrict__ gs, const float* __restrict__ gd,
                const float* __restrict__ af, const float* __restrict__ ab,
                float* __restrict__ logf, float* __restrict__ logb,
                float* __restrict__ mf, float* __restrict__ mb,
                float* __restrict__ cse, float* __restrict__ cqe) {
    mma_gemm<true>(Ahi, Alo, WtL, C, EE, blockIdx.x, src, dst, gs, gd,
                   af, ab, logf, logb, mf, mb, cse, cqe);
}

// ------------------------- prep / CSR ---------------------------------------
struct W6 { const float* p[6]; };

// Wt[l][w][n][k] fp16, K-major
__global__ void prep_w_k(W6 w, __half* __restrict__ out) {
    long idx = (long)blockIdx.x * 256 + threadIdx.x;      // LL*6*256*256
    int k = (int)(idx % WK); long t = idx / WK;
    int n = (int)(t % 256);  t /= 256;
    int wi = (int)(t % 6);   int l = (int)(t / 6);
    out[idx] = __float2half(w.p[wi][((size_t)l * 256 + k) * 256 + n]);
}

__global__ void cvt_k(const float4* __restrict__ x, __half2* __restrict__ hi,
                      __half2* __restrict__ lo, int n4) {
    int i = blockIdx.x * blockDim.x + threadIdx.x;
    if (i >= n4) return;
    float4 v = x[i];
    __half h0 = __float2half(v.x), h1 = __float2half(v.y);
    __half h2 = __float2half(v.z), h3 = __float2half(v.w);
    hi[2*i]   = __halves2half2(h0, h1);
    hi[2*i+1] = __halves2half2(h2, h3);
    lo[2*i]   = __halves2half2(__float2half(v.x - __half2float(h0)),
                               __float2half(v.y - __half2float(h1)));
    lo[2*i+1] = __halves2half2(__float2half(v.z - __half2float(h2)),
                               __float2half(v.w - __half2float(h3)));
}

__global__ void zero_deg_k(int* df, int* db) {
    int i = blockIdx.x*blockDim.x + threadIdx.x;
    if (i < NN) { df[i] = 0; db[i] = 0; }
}
__global__ void hist_k(const int* __restrict__ src, const int* __restrict__ dst,
                       int* df, int* db) {
    int e = blockIdx.x*blockDim.x + threadIdx.x;
    if (e >= EE) return;
    atomicAdd(&df[dst[e]], 1);
    atomicAdd(&db[src[e]], 1);
}
__global__ void scan_k(const int* __restrict__ degf, const int* __restrict__ degb,
                       int* offf, int* offb) {
    __shared__ int s[1024];
    for (int arr = 0; arr < 2; arr++) {
        const int* deg = arr ? degb : degf;
        int* off = arr ? offb : offf;
        int carry = 0;
        if (threadIdx.x == 0) off[0] = 0;
        for (int base = 0; base < NN; base += 1024) {
            int i = base + threadIdx.x;
            s[threadIdx.x] = (i < NN) ? deg[i] : 0;
            __syncthreads();
            for (int d = 1; d < 1024; d <<= 1) {
                int t = (threadIdx.x >= d) ? s[threadIdx.x - d] : 0;
                __syncthreads();
                s[threadIdx.x] += t;
                __syncthreads();
            }
            if (i < NN) off[i+1] = carry + s[threadIdx.x];
            carry += s[1023];
            __syncthreads();
        }
    }
}
__global__ void curcpy_k(const int* offf, const int* offb, int* curf, int* curb) {
    int i = blockIdx.x*blockDim.x + threadIdx.x;
    if (i < NN) { curf[i] = offf[i]; curb[i] = offb[i]; }
}
__global__ void fill_k(const int* __restrict__ src, const int* __restrict__ dst,
                       int* curf, int* curb, int* idxf, int* idxb) {
    int e = blockIdx.x*blockDim.x + threadIdx.x;
    if (e >= EE) return;
    idxf[atomicAdd(&curf[dst[e]], 1)] = e;
    idxb[atomicAdd(&curb[src[e]], 1)] = e;
}

// ------------------------- per-layer small kernels --------------------------
__global__ void init_k(float* mf, float* mb, float* denf, float* denb, float* cols) {
    int i = blockIdx.x*blockDim.x + threadIdx.x;
    if (i < NN) { mf[i] = -INFINITY; mb[i] = -INFINITY; denf[i] = 0.f; denb[i] = 0.f; }
    if (i < 8*FF) cols[i] = 0.f;
}

__global__ void finalize_bn_k(const float* __restrict__ colsum, const float* __restrict__ colsumsq,
                              const float* __restrict__ g, const float* __restrict__ b,
                              float invM, float* __restrict__ scale, float* __restrict__ shift) {
    int f = threadIdx.x;
    float mean = colsum[f] * invM;
    float var  = colsumsq[f] * invM - mean*mean;
    float sc   = g[f] * rsqrtf(var + 1e-5f);
    scale[f] = sc;
    shift[f] = b[f] - mean * sc;
}

__global__ void exp_k(const float* __restrict__ logf, const float* __restrict__ logb,
                      const int* __restrict__ src, const int* __restrict__ dst,
                      const float* __restrict__ mf, const float* __restrict__ mb,
                      float* __restrict__ exf, float* __restrict__ exb,
                      float* __restrict__ denf, float* __restrict__ denb) {
    int i = blockIdx.x*blockDim.x + threadIdx.x;
    if (i >= EE) return;
    int d = dst[i], s = src[i];
    float ef = expf(logf[i] - mf[d]);
    float eb = expf(logb[i] - mb[s]);
    exf[i] = ef; exb[i] = eb;
    atomicAdd(&denf[d], ef);
    atomicAdd(&denb[s], eb);
}

// out = (hi+lo) + relu(x*scale+shift); store back hi/lo; optional fp32 out
__global__ void residual_hl_k(__half2* hi, __half2* lo,
                              const float4* __restrict__ x,
                              const float* __restrict__ scale, const float* __restrict__ shift,
                              float4* __restrict__ outF, int n4, int writeF) {
    int i = blockIdx.x*blockDim.x + threadIdx.x;
    if (i >= n4) return;
    int c4 = i & 63;
    __half2 a0 = hi[2*i], a1 = hi[2*i+1], b0 = lo[2*i], b1 = lo[2*i+1];
    float4 base;
    base.x = __half2float(a0.x) + __half2float(b0.x);
    base.y = __half2float(a0.y) + __half2float(b0.y);
    base.z = __half2float(a1.x) + __half2float(b1.x);
    base.w = __half2float(a1.y) + __half2float(b1.y);
    float4 v  = x[i];
    float4 sc = ((const float4*)scale)[c4];
    float4 sh = ((const float4*)shift)[c4];
    float4 r;
    r.x = base.x + fmaxf(v.x*sc.x + sh.x, 0.f);
    r.y = base.y + fmaxf(v.y*sc.y + sh.y, 0.f);
    r.z = base.z + fmaxf(v.z*sc.z + sh.z, 0.f);
    r.w = base.w + fmaxf(v.w*sc.w + sh.w, 0.f);
    __half h0 = __float2half(r.x), h1 = __float2half(r.y);
    __half h2 = __float2half(r.z), h3 = __float2half(r.w);
    hi[2*i]   = __halves2half2(h0, h1);
    hi[2*i+1] = __halves2half2(h2, h3);
    lo[2*i]   = __halves2half2(__float2half(r.x - __half2float(h0)),
                               __float2half(r.y - __half2float(h1)));
    lo[2*i+1] = __halves2half2(__float2half(r.z - __half2float(h2)),
                               __float2half(r.w - __half2float(h3)));
    if (writeF) outF[i] = r;
}

// CSR gather aggregation + node update + BN stats.
__global__ void gather_node_k(
    const int* __restrict__ offf, const int* __restrict__ idxf,
    const int* __restrict__ offb, const int* __restrict__ idxb,
    const int* __restrict__ src, const int* __restrict__ dst,
    const float* __restrict__ exf, const float* __restrict__ denf,
    const float* __restrict__ exb, const float* __restrict__ denb,
    const float4* __restrict__ hWf, const float4* __restrict__ hWb,
    const float4* __restrict__ hself, float4* __restrict__ htmp,
    float* __restrict__ colsum, float* __restrict__ colsumsq) {
    __shared__ float4 scs[256], scq[256];
    const int sub = threadIdx.x >> 6, c = threadIdx.x & 63;
    float4 csum = make_float4(0,0,0,0), csq = make_float4(0,0,0,0);
    #pragma unroll 1
    for (int nn = 0; nn < 8; nn++) {
        int node = blockIdx.x*32 + sub*8 + nn;
        if (node >= NN) break;
        float invf = 1.f/(denf[node] + 1e-9f);
        float invb = 1.f/(denb[node] + 1e-9f);
        float4 acc = hself[(size_t)node*64 + c];
        int e0 = offf[node], e1 = offf[node+1];
        for (int i = e0; i < e1; i++) {
            int e = idxf[i];
            float a = exf[e]*invf;
            float4 v = hWf[(size_t)src[e]*64 + c];
            acc.x += a*v.x; acc.y += a*v.y; acc.z += a*v.z; acc.w += a*v.w;
        }
        e0 = offb[node]; e1 = offb[node+1];
        for (int i = e0; i < e1; i++) {
            int e = idxb[i];
            float a = exb[e]*invb;
            float4 v = hWb[(size_t)dst[e]*64 + c];
            acc.x += a*v.x; acc.y += a*v.y; acc.z += a*v.z; acc.w += a*v.w;
        }
        htmp[(size_t)node*64 + c] = acc;
        csum.x += acc.x; csum.y += acc.y; csum.z += acc.z; csum.w += acc.w;
        csq.x += acc.x*acc.x; csq.y += acc.y*acc.y; csq.z += acc.z*acc.z; csq.w += acc.w*acc.w;
    }
    scs[threadIdx.x] = csum; scq[threadIdx.x] = csq;
    __syncthreads();
    if (sub == 0) {
        float4 s = scs[c], q = scq[c];
        #pragma unroll
        for (int k = 1; k < 4; k++) {
            float4 t = scs[k*64 + c], u = scq[k*64 + c];
            s.x += t.x; s.y += t.y; s.z += t.z; s.w += t.w;
            q.x += u.x; q.y += u.y; q.z += u.z; q.w += u.w;
        }
        atomicAdd(&colsum[c*4+0], s.x); atomicAdd(&colsum[c*4+1], s.y);
        atomicAdd(&colsum[c*4+2], s.z); atomicAdd(&colsum[c*4+3], s.w);
        atomicAdd(&colsumsq[c*4+0], q.x); atomicAdd(&colsumsq[c*4+1], q.y);
        atomicAdd(&colsumsq[c*4+2], q.z); atomicAdd(&colsumsq[c*4+3], q.w);
    }
}

// ------------------------- host orchestration ------------------------------
static float* symF(const void* s) { void* p = nullptr; cudaGetSymbolAddress(&p, s); return (float*)p; }
static int*   symI(const void* s) { void* p = nullptr; cudaGetSymbolAddress(&p, s); return (int*)p; }
static __half* symH(const void* s) { void* p = nullptr; cudaGetSymbolAddress(&p, s); return (__half*)p; }

extern "C" void kernel_launch(void* const* d_in, const int* in_sizes, int n_in,
                              void* d_out, int out_size) {
    const float* h0   = (const float*)d_in[0];
    const float* e0   = (const float*)d_in[1];
    const int*   src  = (const int*)d_in[2];
    const int*   dst  = (const int*)d_in[3];
    const float* We   = (const float*)d_in[4];
    const float* Ws   = (const float*)d_in[5];
    const float* Wd   = (const float*)d_in[6];
    const float* Wse  = (const float*)d_in[7];
    const float* Wf   = (const float*)d_in[8];
    const float* Wb   = (const float*)d_in[9];
    const float* attf = (const float*)d_in[10];
    const float* attb = (const float*)d_in[11];
    const float* ge   = (const float*)d_in[12];
    const float* be   = (const float*)d_in[13];
    const float* gh   = (const float*)d_in[14];
    const float* bh   = (const float*)d_in[15];

    float* etmp = symF(g_etmp);
    float* hW   = symF(g_hW);
    float* htmp = symF(g_htmp);
    float* logf = symF(g_logf);
    float* logb = symF(g_logb);
    float* exf  = symF(g_exf);
    float* exb  = symF(g_exb);
    float* mf   = symF(g_mf);
    float* mb   = symF(g_mb);
    float* denf = symF(g_denf);
    float* denb = symF(g_denb);
    float* cols = symF(g_cols);
    __half* hhi = symH(g_hhi);
    __half* hlo = symH(g_hlo);
    __half* ehi = symH(g_ehi);
    __half* elo = symH(g_elo);
    __half* Wt  = symH(g_Wt);
    int* degf = symI(g_degf);  int* degb = symI(g_degb);
    int* offf = symI(g_offf);  int* offb = symI(g_offb);
    int* idxf = symI(g_idxf);  int* idxb = symI(g_idxb);

    float* hWs = hW;           float* hWd = hW + NF;
    float* hse = hW + 2*NF;    float* hWf_ = hW + 3*NF;
    float* hWb_ = hW + 4*NF;

    float* cse = cols;         float* cqe = cols + FF;
    float* sce = cols + 2*FF;  float* she = cols + 3*FF;
    float* csh = cols + 4*FF;  float* cqh = cols + 5*FF;
    float* sch = cols + 6*FF;  float* shh = cols + 7*FF;

    float* outH; float* outE;
    if (out_size >= NF + EF)      { outH = (float*)d_out; outE = (float*)d_out + NF; }
    else if (out_size == EF)      { outE = (float*)d_out; outH = htmp; }
    else                          { outH = (float*)d_out; outE = etmp; }

    cudaFuncSetAttribute(node_mma_k, cudaFuncAttributeMaxDynamicSharedMemorySize, SMEMB);
    cudaFuncSetAttribute(edge_mma_k, cudaFuncAttributeMaxDynamicSharedMemorySize, SMEMB);

    // weights (once)
    W6 w6; w6.p[0] = We; w6.p[1] = Ws; w6.p[2] = Wd; w6.p[3] = Wse; w6.p[4] = Wf; w6.p[5] = Wb;
    prep_w_k<<<(LL*6*WSZ)/256, 256>>>(w6, Wt);

    // inputs -> hi/lo (once)
    cvt_k<<<(NF/4 + 255)/256, 256>>>((const float4*)h0, (__half2*)hhi, (__half2*)hlo, NF/4);
    cvt_k<<<(EF/4 + 255)/256, 256>>>((const float4*)e0, (__half2*)ehi, (__half2*)elo, EF/4);

    // CSR (once per launch)
    zero_deg_k<<<(NN+255)/256, 256>>>(degf, degb);
    hist_k<<<(EE+255)/256, 256>>>(src, dst, degf, degb);
    scan_k<<<1, 1024>>>(degf, degb, offf, offb);
    curcpy_k<<<(NN+255)/256, 256>>>(offf, offb, degf, degb);
    fill_k<<<(EE+255)/256, 256>>>(src, dst, degf, degb, idxf, idxb);

    for (int l = 0; l < LL; l++) {
        __half* WtL = Wt + (size_t)l * 6 * WSZ;
        int last = (l == LL-1);

        init_k<<<(NN + 255)/256, 256>>>(mf, mb, denf, denb, cols);

        // node GEMMs: h @ {Ws, Wd, Wself, Wf, Wb}
        O5 p; p.O[0] = hWs; p.O[1] = hWd; p.O[2] = hse; p.O[3] = hWf_; p.O[4] = hWb_;
        node_mma_k<<<dim3((NN + BM - 1)/BM, 1, 5), 512, SMEMB>>>(hhi, hlo, WtL, p, NN);

        // edge GEMM + fused gather/logits/max/BN-stats
        edge_mma_k<<<EE/BM, 512, SMEMB>>>(ehi, elo, WtL, etmp, src, dst, hWs, hWd,
                                          attf + l*FF, attb + l*FF,
                                          logf, logb, mf, mb, cse, cqe);

        finalize_bn_k<<<1, 256>>>(cse, cqe, ge + l*FF, be + l*FF, 1.0f/EE, sce, she);
        exp_k<<<(EE + 255)/256, 256>>>(logf, logb, src, dst, mf, mb, exf, exb, denf, denb);

        // e residual (in-place hi/lo, fp32 out on last layer)
        residual_hl_k<<<(EF/4 + 255)/256, 256>>>((__half2*)ehi, (__half2*)elo,
                                                 (const float4*)etmp, sce, she,
                                                 (float4*)outE, EF/4, last);

        // attention aggregation (CSR gather) + node update + BN stats
        gather_node_k<<<(NN + 31)/32, 256>>>(offf, idxf, offb, idxb, src, dst,
                                             exf, denf, exb, denb,
                                             (const float4*)hWf_, (const float4*)hWb_,
                                             (const float4*)hse, (float4*)htmp, csh, cqh);
        finalize_bn_k<<<1, 256>>>(csh, cqh, gh + l*FF, bh + l*FF, 1.0f/NN, sch, shh);

        // h residual (in-place hi/lo, fp32 out on last layer)
        residual_hl_k<<<(NF/4 + 255)/256, 256>>>((__half2*)hhi, (__half2*)hlo,
                                                 (const float4*)htmp, sch, shh,
                                                 (float4*)outH, NF/4, last);
    }
}

// round 9
// speedup vs baseline: 2.9857x; 1.1478x over previous
#include <cuda_runtime.h>
#include <cuda_fp16.h>
#include <math.h>
#include <stdint.h>

#define NN 50000
#define EE 800000
#define FF 256
#define NF (NN*FF)            // 12,800,000
#define EF (EE*FF)            // 204,800,000
#define LL 4
#define WK 256                // weight: single fp16 [N=256, K=256] K-major
#define WSZ (256*WK)

// GEMM tiling: BM=128, BN=256, BK=64, 512 threads (16 warps, 4x4)
#define BM 128
#define AST 72
#define BST 72
#define ABYTES (BM*AST*2)      // 18432
#define BBYTES (256*BST*2)     // 36864
#define BUFB (ABYTES + BBYTES) // 55296
#define SMEMB (2*BUFB)         // 110592

// ------------------------- scratch (device globals, no allocs) -------------
__device__ float g_etmp[EF];
__device__ float g_hW[5*NF];     // hWs | hWd | hself | hWf | hWb
__device__ float g_htmp[NF];
__device__ float g_logf[EE];
__device__ float g_logb[EE];
__device__ float g_exf[EE];
__device__ float g_exb[EE];
__device__ float g_mf[NN];
__device__ float g_mb[NN];
__device__ float g_denf[NN];
__device__ float g_denb[NN];
__device__ float g_cols[8*FF];
__device__ __half g_hhi[NF];
__device__ __half g_hlo[NF];
__device__ __half g_ehi[EF];
__device__ __half g_elo[EF];
__device__ __half g_Wt[LL*6*WSZ];
// CSR
__device__ int g_degf[NN];
__device__ int g_degb[NN];
__device__ int g_offf[NN+1];
__device__ int g_offb[NN+1];
__device__ int g_idxf[EE];
__device__ int g_idxb[EE];

// ------------------------- helpers -----------------------------------------
__device__ __forceinline__ uint32_t s2u(const void* p) {
    uint32_t a;
    asm("{ .reg .u64 t; cvta.to.shared.u64 t, %1; cvt.u32.u64 %0, t; }" : "=r"(a) : "l"(p));
    return a;
}
__device__ __forceinline__ void cp_async16(uint32_t saddr, const void* g) {
    asm volatile("cp.async.cg.shared.global [%0], [%1], 16;" :: "r"(saddr), "l"(g));
}
__device__ __forceinline__ void ldsm4(uint32_t addr, uint32_t& r0, uint32_t& r1,
                                      uint32_t& r2, uint32_t& r3) {
    asm volatile("ldmatrix.sync.aligned.m8n8.x4.shared.b16 {%0,%1,%2,%3}, [%4];"
                 : "=r"(r0), "=r"(r1), "=r"(r2), "=r"(r3) : "r"(addr));
}
__device__ __forceinline__ void mma16816(float* d, const uint32_t* a, const uint32_t* b) {
    asm volatile(
        "mma.sync.aligned.m16n8k16.row.col.f32.f16.f16.f32 "
        "{%0,%1,%2,%3}, {%4,%5,%6,%7}, {%8,%9}, {%0,%1,%2,%3};"
        : "+f"(d[0]), "+f"(d[1]), "+f"(d[2]), "+f"(d[3])
        : "r"(a[0]), "r"(a[1]), "r"(a[2]), "r"(a[3]), "r"(b[0]), "r"(b[1]));
}
__device__ __forceinline__ void atomicMaxF(float* a, float v) {
    int* ai = (int*)a;
    int old = __float_as_int(*a);
    while (__int_as_float(old) < v) {
        int prev = atomicCAS(ai, old, __float_as_int(v));
        if (prev == old) break;
        old = prev;
    }
}

// ------------------------- fp16 mma GEMM ------------------------------------
// C[tile*128..+128, 0..256) = A@W.
// TERMS=2: hi/lo split over 8 chunks; chunk c: g=c>>1, t=c&1; A=(t?lo:hi).
// TERMS=1: A=hi only, 4 chunks.
// EDGE: adds gs[src]+gd[dst] in epilogue, then attention logits (+segment max)
// and BN column stats in-register (fused).
template<bool EDGE, int TERMS>
__device__ __forceinline__ void mma_gemm(
    const __half* __restrict__ Ahi, const __half* __restrict__ Alo,
    const __half* __restrict__ Bt, float* __restrict__ C, int M, int tile,
    const int* __restrict__ src, const int* __restrict__ dst,
    const float* __restrict__ gs, const float* __restrict__ gd,
    const float* __restrict__ af, const float* __restrict__ ab,
    float* __restrict__ logf, float* __restrict__ logb,
    float* __restrict__ mf, float* __restrict__ mb,
    float* __restrict__ cse, float* __restrict__ cqe)
{
    extern __shared__ __align__(16) char smem[];
    const uint32_t sb = s2u(smem);
    const int tid = threadIdx.x, wid = tid >> 5, lane = tid & 31;
    const int m0 = tile * BM;
    const int NC = 4 * TERMS;

    auto load_chunk = [&](int c, int buf) {
        int g = (TERMS == 2) ? (c >> 1) : c;
        int t = (TERMS == 2) ? (c & 1) : 0;
        const __half* As = t ? Alo : Ahi;
        const int acol = g << 6;
        const int kb = g << 6;
        const uint32_t a_s = sb + buf*BUFB;
        const uint32_t b_s = a_s + ABYTES;
        #pragma unroll
        for (int i = 0; i < 2; i++) {            // A: 128x64 halves = 1024 uint4
            int v = tid + (i << 9); int r = v >> 3, c16 = v & 7;
            uint32_t sa = a_s + (r*AST + (c16 << 3))*2;
            int gr = m0 + r;
            if (EDGE) {
                cp_async16(sa, As + (size_t)gr*256 + acol + (c16 << 3));
            } else {
                if (gr < M) cp_async16(sa, As + (size_t)gr*256 + acol + (c16 << 3));
                else asm volatile("st.shared.v4.b32 [%0], {%1,%1,%1,%1};" :: "r"(sa), "r"(0));
            }
        }
        #pragma unroll
        for (int i = 0; i < 4; i++) {            // B: 256x64 halves = 2048 uint4
            int v = tid + (i << 9); int r = v >> 3, c16 = v & 7;
            cp_async16(b_s + (r*BST + (c16 << 3))*2, Bt + r*WK + kb + (c16 << 3));
        }
        asm volatile("cp.async.commit_group;");
    };

    const int wm = (wid & 3) << 5;               // 0..96
    const int wn = (wid >> 2) << 6;              // 0,64,128,192
    uint32_t a_off[2];
    #pragma unroll
    for (int im = 0; im < 2; im++)
        a_off[im] = ((wm + im*16 + (lane & 15))*AST + ((lane >> 4) << 3))*2;
    const uint32_t b_off = ((wn + ((lane >> 4) << 3) + (lane & 7))*BST
                           + (((lane >> 3) & 1) << 3))*2;

    float acc[2][8][4];
    #pragma unroll
    for (int im = 0; im < 2; im++)
        #pragma unroll
        for (int j = 0; j < 8; j++)
            #pragma unroll
            for (int q = 0; q < 4; q++) acc[im][j][q] = 0.f;

    load_chunk(0, 0);
    int buf = 0;
    for (int c = 0; c < NC; c++) {
        if (c < NC-1) {
            load_chunk(c + 1, buf ^ 1);
            asm volatile("cp.async.wait_group 1;");
        } else {
            asm volatile("cp.async.wait_group 0;");
        }
        __syncthreads();
        const uint32_t a_s = sb + buf*BUFB;
        const uint32_t b_s = a_s + ABYTES;
        #pragma unroll
        for (int ks = 0; ks < 4; ks++) {
            const uint32_t kh2 = (ks << 4)*2;
            uint32_t a[2][4], b[8][2];
            ldsm4(a_s + a_off[0] + kh2, a[0][0], a[0][1], a[0][2], a[0][3]);
            ldsm4(a_s + a_off[1] + kh2, a[1][0], a[1][1], a[1][2], a[1][3]);
            #pragma unroll
            for (int jp = 0; jp < 4; jp++)
                ldsm4(b_s + b_off + jp*(16*BST*2) + kh2,
                      b[2*jp][0], b[2*jp][1], b[2*jp+1][0], b[2*jp+1][1]);
            #pragma unroll
            for (int im = 0; im < 2; im++)
                #pragma unroll
                for (int j = 0; j < 8; j++)
                    mma16816(acc[im][j], a[im], b[j]);
        }
        __syncthreads();
        buf ^= 1;
    }

    // ---------------- epilogue ----------------
    const int gr0 = lane >> 2;
    const int cl0 = (lane & 3) << 1;

    if (!EDGE) {
        #pragma unroll
        for (int im = 0; im < 2; im++)
            #pragma unroll
            for (int half = 0; half < 2; half++) {
                int gm = m0 + wm + im*16 + gr0 + half*8;
                if (gm >= M) continue;
                #pragma unroll
                for (int j = 0; j < 8; j++) {
                    int col = wn + (j << 3) + cl0;
                    *(float2*)(C + (size_t)gm*256 + col) =
                        make_float2(acc[im][j][half*2], acc[im][j][half*2+1]);
                }
            }
        return;
    }

    // EDGE: fused gather + logits + BN stats
    float* sred = (float*)smem;   // [0:128) rowf | [128:256) rowb | [256:512) cs | [512:768) cq
    for (int i = tid; i < 768; i += 512) sred[i] = 0.f;
    __syncthreads();

    float cs[16], cq[16];
    #pragma unroll
    for (int q = 0; q < 16; q++) { cs[q] = 0.f; cq[q] = 0.f; }

    #pragma unroll
    for (int im = 0; im < 2; im++)
        #pragma unroll
        for (int half = 0; half < 2; half++) {
            int rloc = wm + im*16 + gr0 + half*8;
            int gm = m0 + rloc;
            int s = src[gm], d = dst[gm];
            float pf = 0.f, pb = 0.f;
            #pragma unroll
            for (int j = 0; j < 8; j++) {
                int col = wn + (j << 3) + cl0;
                float2 o = make_float2(acc[im][j][half*2], acc[im][j][half*2+1]);
                float2 x = *(const float2*)(gs + (size_t)s*256 + col);
                float2 y = *(const float2*)(gd + (size_t)d*256 + col);
                o.x += x.x + y.x; o.y += x.y + y.y;
                *(float2*)(C + (size_t)gm*256 + col) = o;
                pf += o.x*__ldg(af+col) + o.y*__ldg(af+col+1);
                pb += o.x*__ldg(ab+col) + o.y*__ldg(ab+col+1);
                cs[j*2]   += o.x; cs[j*2+1] += o.y;
                cq[j*2]   += o.x*o.x; cq[j*2+1] += o.y*o.y;
            }
            pf += __shfl_xor_sync(0xFFFFFFFFu, pf, 1);
            pf += __shfl_xor_sync(0xFFFFFFFFu, pf, 2);
            pb += __shfl_xor_sync(0xFFFFFFFFu, pb, 1);
            pb += __shfl_xor_sync(0xFFFFFFFFu, pb, 2);
            if ((lane & 3) == 0) {
                atomicAdd(&sred[rloc], pf);
                atomicAdd(&sred[128 + rloc], pb);
            }
        }
    #pragma unroll
    for (int q = 0; q < 16; q++) {
        cs[q] += __shfl_xor_sync(0xFFFFFFFFu, cs[q], 4);
        cs[q] += __shfl_xor_sync(0xFFFFFFFFu, cs[q], 8);
        cs[q] += __shfl_xor_sync(0xFFFFFFFFu, cs[q], 16);
        cq[q] += __shfl_xor_sync(0xFFFFFFFFu, cq[q], 4);
        cq[q] += __shfl_xor_sync(0xFFFFFFFFu, cq[q], 8);
        cq[q] += __shfl_xor_sync(0xFFFFFFFFu, cq[q], 16);
    }
    if (lane < 4) {
        #pragma unroll
        for (int j = 0; j < 8; j++) {
            int col = wn + (j << 3) + ((lane & 3) << 1);
            atomicAdd(&sred[256 + col],     cs[j*2]);
            atomicAdd(&sred[256 + col + 1], cs[j*2+1]);
            atomicAdd(&sred[512 + col],     cq[j*2]);
            atomicAdd(&sred[512 + col + 1], cq[j*2+1]);
        }
    }
    __syncthreads();
    if (tid < 128) {
        int gm = m0 + tid;
        float lf = sred[tid];       lf = lf > 0.f ? lf : 0.2f*lf;
        float lb = sred[128 + tid]; lb = lb > 0.f ? lb : 0.2f*lb;
        logf[gm] = lf; logb[gm] = lb;
        atomicMaxF(&mf[dst[gm]], lf);
        atomicMaxF(&mb[src[gm]], lb);
    } else if (tid < 384) {
        int col = tid - 128;
        atomicAdd(&cse[col], sred[256 + col]);
        atomicAdd(&cqe[col], sred[512 + col]);
    }
}

struct O5 { float* O[5]; };

__global__ __launch_bounds__(512)
void node_mma_k(const __half* __restrict__ Ahi, const __half* __restrict__ Alo,
                const __half* __restrict__ WtL, O5 p, int M) {
    mma_gemm<false, 2>(Ahi, Alo, WtL + (size_t)(blockIdx.z + 1)*WSZ, p.O[blockIdx.z],
                       M, blockIdx.x, nullptr, nullptr, nullptr, nullptr,
                       nullptr, nullptr, nullptr, nullptr, nullptr, nullptr, nullptr, nullptr);
}

__global__ __launch_bounds__(512)
void edge_mma_k(const __half* __restrict__ Ahi,
                const __half* __restrict__ WtL, float* __restrict__ C,
                const int* __restrict__ src, const int* __restrict__ dst,
                const float* __restrict__ gs, const float* __restrict__ gd,
                const float* __restrict__ af, const float* __restrict__ ab,
                float* __restrict__ logf, float* __restrict__ logb,
                float* __restrict__ mf, float* __restrict__ mb,
                float* __restrict__ cse, float* __restrict__ cqe) {
    mma_gemm<true, 1>(Ahi, Ahi, WtL, C, EE, blockIdx.x, src, dst, gs, gd,
                      af, ab, logf, logb, mf, mb, cse, cqe);
}

// ------------------------- prep / CSR ---------------------------------------
struct W6 { const float* p[6]; };

// Wt[l][w][n][k] fp16, K-major
__global__ void prep_w_k(W6 w, __half* __restrict__ out) {
    long idx = (long)blockIdx.x * 256 + threadIdx.x;      // LL*6*256*256
    int k = (int)(idx % WK); long t = idx / WK;
    int n = (int)(t % 256);  t /= 256;
    int wi = (int)(t % 6);   int l = (int)(t / 6);
    out[idx] = __float2half(w.p[wi][((size_t)l * 256 + k) * 256 + n]);
}

__global__ void cvt_k(const float4* __restrict__ x, __half2* __restrict__ hi,
                      __half2* __restrict__ lo, int n4) {
    int i = blockIdx.x * blockDim.x + threadIdx.x;
    if (i >= n4) return;
    float4 v = x[i];
    __half h0 = __float2half(v.x), h1 = __float2half(v.y);
    __half h2 = __float2half(v.z), h3 = __float2half(v.w);
    hi[2*i]   = __halves2half2(h0, h1);
    hi[2*i+1] = __halves2half2(h2, h3);
    lo[2*i]   = __halves2half2(__float2half(v.x - __half2float(h0)),
                               __float2half(v.y - __half2float(h1)));
    lo[2*i+1] = __halves2half2(__float2half(v.z - __half2float(h2)),
                               __float2half(v.w - __half2float(h3)));
}

__global__ void zero_deg_k(int* df, int* db) {
    int i = blockIdx.x*blockDim.x + threadIdx.x;
    if (i < NN) { df[i] = 0; db[i] = 0; }
}
__global__ void hist_k(const int* __restrict__ src, const int* __restrict__ dst,
                       int* df, int* db) {
    int e = blockIdx.x*blockDim.x + threadIdx.x;
    if (e >= EE) return;
    atomicAdd(&df[dst[e]], 1);
    atomicAdd(&db[src[e]], 1);
}
__global__ void scan_k(const int* __restrict__ degf, const int* __restrict__ degb,
                       int* offf, int* offb) {
    __shared__ int s[1024];
    for (int arr = 0; arr < 2; arr++) {
        const int* deg = arr ? degb : degf;
        int* off = arr ? offb : offf;
        int carry = 0;
        if (threadIdx.x == 0) off[0] = 0;
        for (int base = 0; base < NN; base += 1024) {
            int i = base + threadIdx.x;
            s[threadIdx.x] = (i < NN) ? deg[i] : 0;
            __syncthreads();
            for (int d = 1; d < 1024; d <<= 1) {
                int t = (threadIdx.x >= d) ? s[threadIdx.x - d] : 0;
                __syncthreads();
                s[threadIdx.x] += t;
                __syncthreads();
            }
            if (i < NN) off[i+1] = carry + s[threadIdx.x];
            carry += s[1023];
            __syncthreads();
        }
    }
}
__global__ void curcpy_k(const int* offf, const int* offb, int* curf, int* curb) {
    int i = blockIdx.x*blockDim.x + threadIdx.x;
    if (i < NN) { curf[i] = offf[i]; curb[i] = offb[i]; }
}
__global__ void fill_k(const int* __restrict__ src, const int* __restrict__ dst,
                       int* curf, int* curb, int* idxf, int* idxb) {
    int e = blockIdx.x*blockDim.x + threadIdx.x;
    if (e >= EE) return;
    idxf[atomicAdd(&curf[dst[e]], 1)] = e;
    idxb[atomicAdd(&curb[src[e]], 1)] = e;
}

// ------------------------- per-layer small kernels --------------------------
__global__ void init_k(float* mf, float* mb, float* denf, float* denb, float* cols) {
    int i = blockIdx.x*blockDim.x + threadIdx.x;
    if (i < NN) { mf[i] = -INFINITY; mb[i] = -INFINITY; denf[i] = 0.f; denb[i] = 0.f; }
    if (i < 8*FF) cols[i] = 0.f;
}

__global__ void finalize_bn_k(const float* __restrict__ colsum, const float* __restrict__ colsumsq,
                              const float* __restrict__ g, const float* __restrict__ b,
                              float invM, float* __restrict__ scale, float* __restrict__ shift) {
    int f = threadIdx.x;
    float mean = colsum[f] * invM;
    float var  = colsumsq[f] * invM - mean*mean;
    float sc   = g[f] * rsqrtf(var + 1e-5f);
    scale[f] = sc;
    shift[f] = b[f] - mean * sc;
}

__global__ void exp_k(const float* __restrict__ logf, const float* __restrict__ logb,
                      const int* __restrict__ src, const int* __restrict__ dst,
                      const float* __restrict__ mf, const float* __restrict__ mb,
                      float* __restrict__ exf, float* __restrict__ exb,
                      float* __restrict__ denf, float* __restrict__ denb) {
    int i = blockIdx.x*blockDim.x + threadIdx.x;
    if (i >= EE) return;
    int d = dst[i], s = src[i];
    float ef = expf(logf[i] - mf[d]);
    float eb = expf(logb[i] - mb[s]);
    exf[i] = ef; exb[i] = eb;
    atomicAdd(&denf[d], ef);
    atomicAdd(&denb[s], eb);
}

// out = (hi+lo) + relu(x*scale+shift); store back hi/lo; optional fp32 out
__global__ void residual_hl_k(__half2* hi, __half2* lo,
                              const float4* __restrict__ x,
                              const float* __restrict__ scale, const float* __restrict__ shift,
                              float4* __restrict__ outF, int n4, int writeF) {
    int i = blockIdx.x*blockDim.x + threadIdx.x;
    if (i >= n4) return;
    int c4 = i & 63;
    __half2 a0 = hi[2*i], a1 = hi[2*i+1], b0 = lo[2*i], b1 = lo[2*i+1];
    float4 base;
    base.x = __half2float(a0.x) + __half2float(b0.x);
    base.y = __half2float(a0.y) + __half2float(b0.y);
    base.z = __half2float(a1.x) + __half2float(b1.x);
    base.w = __half2float(a1.y) + __half2float(b1.y);
    float4 v  = x[i];
    float4 sc = ((const float4*)scale)[c4];
    float4 sh = ((const float4*)shift)[c4];
    float4 r;
    r.x = base.x + fmaxf(v.x*sc.x + sh.x, 0.f);
    r.y = base.y + fmaxf(v.y*sc.y + sh.y, 0.f);
    r.z = base.z + fmaxf(v.z*sc.z + sh.z, 0.f);
    r.w = base.w + fmaxf(v.w*sc.w + sh.w, 0.f);
    __half h0 = __float2half(r.x), h1 = __float2half(r.y);
    __half h2 = __float2half(r.z), h3 = __float2half(r.w);
    hi[2*i]   = __halves2half2(h0, h1);
    hi[2*i+1] = __halves2half2(h2, h3);
    lo[2*i]   = __halves2half2(__float2half(r.x - __half2float(h0)),
                               __float2half(r.y - __half2float(h1)));
    lo[2*i+1] = __halves2half2(__float2half(r.z - __half2float(h2)),
                               __float2half(r.w - __half2float(h3)));
    if (writeF) outF[i] = r;
}

// CSR gather aggregation + node update + BN stats.
__global__ void gather_node_k(
    const int* __restrict__ offf, const int* __restrict__ idxf,
    const int* __restrict__ offb, const int* __restrict__ idxb,
    const int* __restrict__ src, const int* __restrict__ dst,
    const float* __restrict__ exf, const float* __restrict__ denf,
    const float* __restrict__ exb, const float* __restrict__ denb,
    const float4* __restrict__ hWf, const float4* __restrict__ hWb,
    const float4* __restrict__ hself, float4* __restrict__ htmp,
    float* __restrict__ colsum, float* __restrict__ colsumsq) {
    __shared__ float4 scs[256], scq[256];
    const int sub = threadIdx.x >> 6, c = threadIdx.x & 63;
    float4 csum = make_float4(0,0,0,0), csq = make_float4(0,0,0,0);
    #pragma unroll 1
    for (int nn = 0; nn < 8; nn++) {
        int node = blockIdx.x*32 + sub*8 + nn;
        if (node >= NN) break;
        float invf = 1.f/(denf[node] + 1e-9f);
        float invb = 1.f/(denb[node] + 1e-9f);
        float4 acc = hself[(size_t)node*64 + c];
        int e0 = offf[node], e1 = offf[node+1];
        for (int i = e0; i < e1; i++) {
            int e = idxf[i];
            float a = exf[e]*invf;
            float4 v = hWf[(size_t)src[e]*64 + c];
            acc.x += a*v.x; acc.y += a*v.y; acc.z += a*v.z; acc.w += a*v.w;
        }
        e0 = offb[node]; e1 = offb[node+1];
        for (int i = e0; i < e1; i++) {
            int e = idxb[i];
            float a = exb[e]*invb;
            float4 v = hWb[(size_t)dst[e]*64 + c];
            acc.x += a*v.x; acc.y += a*v.y; acc.z += a*v.z; acc.w += a*v.w;
        }
        htmp[(size_t)node*64 + c] = acc;
        csum.x += acc.x; csum.y += acc.y; csum.z += acc.z; csum.w += acc.w;
        csq.x += acc.x*acc.x; csq.y += acc.y*acc.y; csq.z += acc.z*acc.z; csq.w += acc.w*acc.w;
    }
    scs[threadIdx.x] = csum; scq[threadIdx.x] = csq;
    __syncthreads();
    if (sub == 0) {
        float4 s = scs[c], q = scq[c];
        #pragma unroll
        for (int k = 1; k < 4; k++) {
            float4 t = scs[k*64 + c], u = scq[k*64 + c];
            s.x += t.x; s.y += t.y; s.z += t.z; s.w += t.w;
            q.x += u.x; q.y += u.y; q.z += u.z; q.w += u.w;
        }
        atomicAdd(&colsum[c*4+0], s.x); atomicAdd(&colsum[c*4+1], s.y);
        atomicAdd(&colsum[c*4+2], s.z); atomicAdd(&colsum[c*4+3], s.w);
        atomicAdd(&colsumsq[c*4+0], q.x); atomicAdd(&colsumsq[c*4+1], q.y);
        atomicAdd(&colsumsq[c*4+2], q.z); atomicAdd(&colsumsq[c*4+3], q.w);
    }
}

// ------------------------- host orchestration ------------------------------
static float* symF(const void* s) { void* p = nullptr; cudaGetSymbolAddress(&p, s); return (float*)p; }
static int*   symI(const void* s) { void* p = nullptr; cudaGetSymbolAddress(&p, s); return (int*)p; }
static __half* symH(const void* s) { void* p = nullptr; cudaGetSymbolAddress(&p, s); return (__half*)p; }

extern "C" void kernel_launch(void* const* d_in, const int* in_sizes, int n_in,
                              void* d_out, int out_size) {
    const float* h0   = (const float*)d_in[0];
    const float* e0   = (const float*)d_in[1];
    const int*   src  = (const int*)d_in[2];
    const int*   dst  = (const int*)d_in[3];
    const float* We   = (const float*)d_in[4];
    const float* Ws   = (const float*)d_in[5];
    const float* Wd   = (const float*)d_in[6];
    const float* Wse  = (const float*)d_in[7];
    const float* Wf   = (const float*)d_in[8];
    const float* Wb   = (const float*)d_in[9];
    const float* attf = (const float*)d_in[10];
    const float* attb = (const float*)d_in[11];
    const float* ge   = (const float*)d_in[12];
    const float* be   = (const float*)d_in[13];
    const float* gh   = (const float*)d_in[14];
    const float* bh   = (const float*)d_in[15];

    float* etmp = symF(g_etmp);
    float* hW   = symF(g_hW);
    float* htmp = symF(g_htmp);
    float* logf = symF(g_logf);
    float* logb = symF(g_logb);
    float* exf  = symF(g_exf);
    float* exb  = symF(g_exb);
    float* mf   = symF(g_mf);
    float* mb   = symF(g_mb);
    float* denf = symF(g_denf);
    float* denb = symF(g_denb);
    float* cols = symF(g_cols);
    __half* hhi = symH(g_hhi);
    __half* hlo = symH(g_hlo);
    __half* ehi = symH(g_ehi);
    __half* elo = symH(g_elo);
    __half* Wt  = symH(g_Wt);
    int* degf = symI(g_degf);  int* degb = symI(g_degb);
    int* offf = symI(g_offf);  int* offb = symI(g_offb);
    int* idxf = symI(g_idxf);  int* idxb = symI(g_idxb);

    float* hWs = hW;           float* hWd = hW + NF;
    float* hse = hW + 2*NF;    float* hWf_ = hW + 3*NF;
    float* hWb_ = hW + 4*NF;

    float* cse = cols;         float* cqe = cols + FF;
    float* sce = cols + 2*FF;  float* she = cols + 3*FF;
    float* csh = cols + 4*FF;  float* cqh = cols + 5*FF;
    float* sch = cols + 6*FF;  float* shh = cols + 7*FF;

    float* outH; float* outE;
    if (out_size >= NF + EF)      { outH = (float*)d_out; outE = (float*)d_out + NF; }
    else if (out_size == EF)      { outE = (float*)d_out; outH = htmp; }
    else                          { outH = (float*)d_out; outE = etmp; }

    cudaFuncSetAttribute(node_mma_k, cudaFuncAttributeMaxDynamicSharedMemorySize, SMEMB);
    cudaFuncSetAttribute(edge_mma_k, cudaFuncAttributeMaxDynamicSharedMemorySize, SMEMB);

    // weights (once)
    W6 w6; w6.p[0] = We; w6.p[1] = Ws; w6.p[2] = Wd; w6.p[3] = Wse; w6.p[4] = Wf; w6.p[5] = Wb;
    prep_w_k<<<(LL*6*WSZ)/256, 256>>>(w6, Wt);

    // inputs -> hi/lo (once)
    cvt_k<<<(NF/4 + 255)/256, 256>>>((const float4*)h0, (__half2*)hhi, (__half2*)hlo, NF/4);
    cvt_k<<<(EF/4 + 255)/256, 256>>>((const float4*)e0, (__half2*)ehi, (__half2*)elo, EF/4);

    // CSR (once per launch)
    zero_deg_k<<<(NN+255)/256, 256>>>(degf, degb);
    hist_k<<<(EE+255)/256, 256>>>(src, dst, degf, degb);
    scan_k<<<1, 1024>>>(degf, degb, offf, offb);
    curcpy_k<<<(NN+255)/256, 256>>>(offf, offb, degf, degb);
    fill_k<<<(EE+255)/256, 256>>>(src, dst, degf, degb, idxf, idxb);

    for (int l = 0; l < LL; l++) {
        __half* WtL = Wt + (size_t)l * 6 * WSZ;
        int last = (l == LL-1);

        init_k<<<(NN + 255)/256, 256>>>(mf, mb, denf, denb, cols);

        // node GEMMs: h @ {Ws, Wd, Wself, Wf, Wb}  (2-term hi/lo)
        O5 p; p.O[0] = hWs; p.O[1] = hWd; p.O[2] = hse; p.O[3] = hWf_; p.O[4] = hWb_;
        node_mma_k<<<dim3((NN + BM - 1)/BM, 1, 5), 512, SMEMB>>>(hhi, hlo, WtL, p, NN);

        // edge GEMM (1-term, ehi only) + fused gather/logits/max/BN-stats
        edge_mma_k<<<EE/BM, 512, SMEMB>>>(ehi, WtL, etmp, src, dst, hWs, hWd,
                                          attf + l*FF, attb + l*FF,
                                          logf, logb, mf, mb, cse, cqe);

        finalize_bn_k<<<1, 256>>>(cse, cqe, ge + l*FF, be + l*FF, 1.0f/EE, sce, she);
        exp_k<<<(EE + 255)/256, 256>>>(logf, logb, src, dst, mf, mb, exf, exb, denf, denb);

        // e residual (in-place hi/lo, fp32 out on last layer)
        residual_hl_k<<<(EF/4 + 255)/256, 256>>>((__half2*)ehi, (__half2*)elo,
                                                 (const float4*)etmp, sce, she,
                                                 (float4*)outE, EF/4, last);

        // attention aggregation (CSR gather) + node update + BN stats
        gather_node_k<<<(NN + 31)/32, 256>>>(offf, idxf, offb, idxb, src, dst,
                                             exf, denf, exb, denb,
                                             (const float4*)hWf_, (const float4*)hWb_,
                                             (const float4*)hse, (float4*)htmp, csh, cqh);
        finalize_bn_k<<<1, 256>>>(csh, cqh, gh + l*FF, bh + l*FF, 1.0f/NN, sch, shh);

        // h residual (in-place hi/lo, fp32 out on last layer)
        residual_hl_k<<<(NF/4 + 255)/256, 256>>>((__half2*)hhi, (__half2*)hlo,
                                                 (const float4*)htmp, sch, shh,
                                                 (float4*)outH, NF/4, last);
    }
}